// round 14
// baseline (speedup 1.0000x reference)
#include <cuda_runtime.h>
#include <cuda_bf16.h>
#include <math.h>
#include <stdint.h>

#define BATCH 4
#define TT 2048
#define DD 512
#define HH 4
#define M_ROWS 8192
#define KQ 1536          // augmented K for qkvg GEMM (hi|hi|lo x hi|lo|hi)
#define KO 192           // augmented K for out GEMM

// ---------------------------------------------------------------------------
// Global scratch (device globals; no allocation allowed)
// ---------------------------------------------------------------------------
__device__ uint4 g_xhi[524288];     // 8MB  [8192][512] bf16
__device__ uint4 g_xlo[524288];     // 8MB
__device__ uint4 g_wcatT[49152];    // 1.5MB [256][1536] bf16 (W_hi|W_lo|W_hi)^T
__device__ uint4 g_zhi[65536];      // 1MB  [8192][64] bf16
__device__ uint4 g_zlo[65536];      // 1MB
__device__ uint4 g_woT[12288];      // 384KB [512][192] bf16 (Wo_hi|Wo_lo|Wo_hi)^T
__device__ float g_vg[M_ROWS*128];  // 4MB  v|g fp32 (cols 0-63 v, 64-127 g)
__device__ float g_a[HH*M_ROWS];    // [h][row]
__device__ float g_bid[HH*M_ROWS];  // [h][row]
// scan intermediates (SoA by global lane id gl = chunk*32 + lane)
__device__ float g_p0[16384], g_p1[16384];
__device__ float g_sm[16384], g_sd[16384];
__device__ float g_sn[16][16384];
__device__ float g_aggA[512];       // per-chunk total sum of a

// ---------------------------------------------------------------------------
// Helpers
// ---------------------------------------------------------------------------
__device__ __forceinline__ uint32_t smem_u32(const void* p) {
    uint32_t a;
    asm("{ .reg .u64 t; cvta.to.shared.u64 t, %1; cvt.u32.u64 %0, t; }" : "=r"(a) : "l"(p));
    return a;
}
#define SWZ(x) ((x) ^ (((x) >> 3) & 0x70))

__device__ __forceinline__ void cpa16(uint32_t saddr, const void* g) {
    asm volatile("cp.async.cg.shared.global [%0], [%1], 16;" :: "r"(saddr), "l"(g));
}
#define CP_COMMIT() asm volatile("cp.async.commit_group;" ::: "memory")
#define CP_WAIT0()  asm volatile("cp.async.wait_group 0;" ::: "memory")

__device__ __forceinline__ void mma_bf16(float c[4], const uint32_t a[4], const uint32_t b[2]) {
    asm volatile("mma.sync.aligned.m16n8k16.row.col.f32.bf16.bf16.f32 "
        "{%0,%1,%2,%3}, {%4,%5,%6,%7}, {%8,%9}, {%0,%1,%2,%3};"
        : "+f"(c[0]), "+f"(c[1]), "+f"(c[2]), "+f"(c[3])
        : "r"(a[0]), "r"(a[1]), "r"(a[2]), "r"(a[3]), "r"(b[0]), "r"(b[1]));
}

__device__ __forceinline__ void split2(float a, float b, uint32_t& hi, uint32_t& lo) {
    __nv_bfloat16 ha = __float2bfloat16(a), hb = __float2bfloat16(b);
    float ra = a - __bfloat162float(ha), rb = b - __bfloat162float(hb);
    __nv_bfloat162 H, L;
    H.x = ha; H.y = hb;
    L.x = __float2bfloat16(ra); L.y = __float2bfloat16(rb);
    hi = *reinterpret_cast<uint32_t*>(&H);
    lo = *reinterpret_cast<uint32_t*>(&L);
}

#define MSENT -1e30f

// online-softmax step (inclusive update), branchless
__device__ __forceinline__ void sm_step(float& m, float& d, float n[16],
                                        float p, const float* v) {
    float4 v0 = *(const float4*)&v[0],  v1 = *(const float4*)&v[4];
    float4 v2 = *(const float4*)&v[8],  v3 = *(const float4*)&v[12];
    float vv[16] = {v0.x,v0.y,v0.z,v0.w, v1.x,v1.y,v1.z,v1.w,
                    v2.x,v2.y,v2.z,v2.w, v3.x,v3.y,v3.z,v3.w};
    float M = fmaxf(m, p);
    float sm = __expf(m - M), sp = __expf(p - M);
    d = d * sm + sp;
    #pragma unroll
    for (int i = 0; i < 16; i++) n[i] = n[i] * sm + vv[i] * sp;
    m = M;
}

// state combine: self(right) <- other(left) ⊕ self
__device__ __forceinline__ void sm_comb(float& m, float& d, float n[16],
                                        float om, float od, const float on[16]) {
    float M = fmaxf(om, m);
    float so = __expf(om - M), ss = __expf(m - M);
    d = od * so + d * ss;
    #pragma unroll
    for (int i = 0; i < 16; i++) n[i] = on[i] * so + n[i] * ss;
    m = M;
}

// ---------------------------------------------------------------------------
// K1: merged setup. Blocks [0,1024): x -> (x_hi,x_lo) + a-projection.
//     Blocks [1024,1664): pack weights.
// ---------------------------------------------------------------------------
__global__ void __launch_bounds__(256) setup_kernel(
    const float* __restrict__ X,  const float* __restrict__ Wa,
    const float* __restrict__ ba, const float* __restrict__ Wq,
    const float* __restrict__ Wk, const float* __restrict__ Wv,
    const float* __restrict__ Wg, const float* __restrict__ Wo)
{
    if (blockIdx.x < 1024) {
        int row  = (blockIdx.x * 256 + threadIdx.x) >> 5;
        int lane = threadIdx.x & 31;
        const float* xr = X + (size_t)row * DD;
        int c0 = lane * 16;

        float xv[16];
        #pragma unroll
        for (int i = 0; i < 4; i++) {
            float4 v = *(const float4*)&xr[c0 + i * 4];
            xv[i*4+0] = v.x; xv[i*4+1] = v.y; xv[i*4+2] = v.z; xv[i*4+3] = v.w;
        }

        float4 acc = make_float4(0.f, 0.f, 0.f, 0.f);
        #pragma unroll
        for (int i = 0; i < 16; i++) {
            float4 w = *(const float4*)&Wa[(size_t)(c0 + i) * 4];
            acc.x += xv[i] * w.x; acc.y += xv[i] * w.y;
            acc.z += xv[i] * w.z; acc.w += xv[i] * w.w;
        }

        uint32_t hi[8], lo[8];
        #pragma unroll
        for (int i = 0; i < 8; i++) split2(xv[2*i], xv[2*i+1], hi[i], lo[i]);

        size_t base = (size_t)row * 64 + lane * 2;
        g_xhi[base + 0] = make_uint4(hi[0], hi[1], hi[2], hi[3]);
        g_xhi[base + 1] = make_uint4(hi[4], hi[5], hi[6], hi[7]);
        g_xlo[base + 0] = make_uint4(lo[0], lo[1], lo[2], lo[3]);
        g_xlo[base + 1] = make_uint4(lo[4], lo[5], lo[6], lo[7]);

        #pragma unroll
        for (int off = 16; off > 0; off >>= 1) {
            acc.x += __shfl_down_sync(0xffffffffu, acc.x, off);
            acc.y += __shfl_down_sync(0xffffffffu, acc.y, off);
            acc.z += __shfl_down_sync(0xffffffffu, acc.z, off);
            acc.w += __shfl_down_sync(0xffffffffu, acc.w, off);
        }
        if (lane == 0) {
            float zz[4] = {acc.x + ba[0], acc.y + ba[1], acc.z + ba[2], acc.w + ba[3]};
            #pragma unroll
            for (int h = 0; h < 4; h++) {
                float z = zz[h];
                float sp = fmaxf(z, 0.f) + log1pf(expf(-fabsf(z)));
                g_a[h * M_ROWS + row] = -sp;
            }
        }
    } else {
        int idx = (blockIdx.x - 1024) * 256 + threadIdx.x;
        if (idx < 131072) {
            int k = idx >> 8, n = idx & 255;
            float v;
            if      (n < 64)  v = Wq[k*64 + n];
            else if (n < 128) v = Wk[k*64 + (n-64)];
            else if (n < 192) v = Wv[k*64 + (n-128)];
            else              v = Wg[k*64 + (n-192)];
            __nv_bfloat16 h = __float2bfloat16(v);
            __nv_bfloat16 l = __float2bfloat16(v - __bfloat162float(h));
            __nv_bfloat16* W = (__nv_bfloat16*)g_wcatT;
            W[(size_t)n * KQ +        k] = h;
            W[(size_t)n * KQ +  512 + k] = l;
            W[(size_t)n * KQ + 1024 + k] = h;
        } else {
            int j = idx - 131072;
            int k = j >> 9, n = j & 511;
            float v = Wo[(size_t)k * 512 + n];
            __nv_bfloat16 h = __float2bfloat16(v);
            __nv_bfloat16 l = __float2bfloat16(v - __bfloat162float(h));
            __nv_bfloat16* W = (__nv_bfloat16*)g_woT;
            W[(size_t)n * KO +       k] = h;
            W[(size_t)n * KO +  64 + k] = l;
            W[(size_t)n * KO + 128 + k] = h;
        }
    }
}

// ---------------------------------------------------------------------------
// K2: qkvg GEMM, 512 threads. BM=64, BN=256, grid (128 mtiles) = one wave.
// A read ONCE. Warps 2m x 8n, warp tile 32x32. 3-stage pipeline,
// 40KB/stage: A 8KB | B 32KB. Epilogue: wn<128 -> bid (via smem), else v|g.
// ---------------------------------------------------------------------------
__global__ void __launch_bounds__(512) gemm_qkvg_mma() {
    extern __shared__ __align__(1024) char smem[];
    uint32_t sb = smem_u32(smem);
    int tid = threadIdx.x, wid = tid >> 5, lane = tid & 31;
    int mtile = blockIdx.x;

    const __nv_bfloat16* B = (const __nv_bfloat16*)g_wcatT;   // all 256 n-rows
    size_t aoff = (size_t)mtile * 64 * 512;
    auto getA = [&](int kc) -> const __nv_bfloat16* {
        const __nv_bfloat16* base = (kc < 16) ? (const __nv_bfloat16*)g_xhi
                                              : (const __nv_bfloat16*)g_xlo;
        int kk = (kc < 8) ? kc : ((kc < 16) ? kc - 8 : kc - 16);
        return base + aoff + kk * 64;
    };

    int wm = (wid & 1) * 32, wn = (wid >> 1) * 32;
    int lr = lane & 7, sel = lane >> 3;
    int arow = wm + lr + (sel & 1) * 8;
    int acol = (sel >> 1) * 16;
    int brow = wn + lr;
    int bcol = (sel & 1) * 16;

    float acc[2][4][4] = {};

    auto load = [&](int kc, int s) {
        uint32_t base = sb + (uint32_t)s * 40960;
        const __nv_bfloat16* Ak = getA(kc);
        const __nv_bfloat16* Bk = B + kc * 64;
        {   // A: 64 rows x 64 cols = 512 uint4, 1 per thread
            int r = tid >> 3, ch = tid & 7;
            cpa16(base + SWZ((uint32_t)(r * 128 + ch * 16)),
                  Ak + (size_t)r * 512 + ch * 8);
        }
        #pragma unroll
        for (int j = 0; j < 4; j++) {   // B: 256 rows x 64 cols = 2048 uint4
            int idx = j * 512 + tid;
            int r = idx >> 3, ch = idx & 7;
            cpa16(base + 8192 + SWZ((uint32_t)(r * 128 + ch * 16)),
                  Bk + (size_t)r * KQ + ch * 8);
        }
        CP_COMMIT();
    };

    load(0, 0);
    load(1, 1);

    for (int kc = 0; kc < 24; kc++) {
        asm volatile("cp.async.wait_group 1;" ::: "memory");
        __syncthreads();
        if (kc + 2 < 24) load(kc + 2, (kc + 2) % 3); else CP_COMMIT();

        uint32_t Ab = sb + (uint32_t)(kc % 3) * 40960;
        uint32_t Bb = Ab + 8192;
        #pragma unroll
        for (int ks = 0; ks < 4; ks++) {
            uint32_t a[2][4], b[4][2];
            #pragma unroll
            for (int mf = 0; mf < 2; mf++) {
                uint32_t addr = Ab + SWZ((uint32_t)((arow + mf * 16) * 128 + acol + ks * 32));
                asm volatile("ldmatrix.sync.aligned.m8n8.x4.shared.b16 {%0,%1,%2,%3}, [%4];"
                    : "=r"(a[mf][0]), "=r"(a[mf][1]), "=r"(a[mf][2]), "=r"(a[mf][3])
                    : "r"(addr));
            }
            #pragma unroll
            for (int nf = 0; nf < 4; nf++) {
                uint32_t addr = Bb + SWZ((uint32_t)((brow + nf * 8) * 128 + bcol + ks * 32));
                asm volatile("ldmatrix.sync.aligned.m8n8.x2.shared.b16 {%0,%1}, [%2];"
                    : "=r"(b[nf][0]), "=r"(b[nf][1])
                    : "r"(addr));
            }
            #pragma unroll
            for (int mf = 0; mf < 2; mf++)
                #pragma unroll
                for (int nf = 0; nf < 4; nf++)
                    mma_bf16(acc[mf][nf], a[mf], b[nf]);
        }
    }
    CP_WAIT0();

    int er = lane >> 2, ec = (lane & 3) * 2;
    int m0 = mtile * 64;

    __syncthreads();                       // mainloop smem free
    float* S = (float*)smem;               // 64x128 fp32 = 32KB, xor-swizzled

    if (wn < 128) {
        int xm = er << 4;
        #pragma unroll
        for (int mf = 0; mf < 2; mf++)
            #pragma unroll
            for (int nf = 0; nf < 4; nf++) {
                int r = wm + mf * 16 + er;
                int c = (wn + nf * 8 + ec) ^ xm;
                *(float2*)&S[r * 128 + c]       = make_float2(acc[mf][nf][0], acc[mf][nf][1]);
                *(float2*)&S[(r + 8) * 128 + c] = make_float2(acc[mf][nf][2], acc[mf][nf][3]);
            }
    } else {
        #pragma unroll
        for (int mf = 0; mf < 2; mf++)
            #pragma unroll
            for (int nf = 0; nf < 4; nf++) {
                int r = m0 + wm + mf * 16 + er;
                int c = (wn - 128) + nf * 8 + ec;
                *(float2*)&g_vg[(size_t)r * 128 + c]       = make_float2(acc[mf][nf][0], acc[mf][nf][1]);
                *(float2*)&g_vg[(size_t)(r + 8) * 128 + c] = make_float2(acc[mf][nf][2], acc[mf][nf][3]);
            }
    }
    __syncthreads();

    if (tid < 256) {
        int m = tid >> 2, h = tid & 3;     // 64 rows x 4 heads
        int x = (m & 7) << 4;
        const float* q = &S[m * 128 + ((h * 16) ^ x)];
        const float* k = &S[m * 128 + ((64 + h * 16) ^ x)];
        float s = 0.f;
        #pragma unroll
        for (int i = 0; i < 16; i++) s += q[i] * k[i];
        g_bid[(size_t)h * M_ROWS + m0 + m] = s * 0.25f;
    }
}

// ---------------------------------------------------------------------------
// Scan: 512 chunks (16 bh x 32 chunks of 64 steps), 1 warp per chunk.
// ---------------------------------------------------------------------------
#define WSHFL_STATE(om, od, on, off)                                        \
    do {                                                                    \
        om = __shfl_up_sync(0xffffffffu, m, off);                           \
        od = __shfl_up_sync(0xffffffffu, d, off);                           \
        _Pragma("unroll")                                                   \
        for (int _i = 0; _i < 16; _i++)                                     \
            on[_i] = __shfl_up_sync(0xffffffffu, n[_i], off);               \
    } while (0)

// S1: per-chunk local scan; stores p, per-lane inclusive states, chunk sumA
__global__ void __launch_bounds__(128) scan_part1() {
    int warp = threadIdx.x >> 5, lane = threadIdx.x & 31;
    int chunk = blockIdx.x * 4 + warp;
    int bh = chunk >> 5, c = chunk & 31;
    int b = bh >> 2, h = bh & 3;
    int row = b * TT + c * 64 + lane * 2;
    int gl = chunk * 32 + lane;

    const float* A   = g_a   + (size_t)h * M_ROWS;
    const float* BID = g_bid + (size_t)h * M_ROWS;
    float a0 = A[row], a1 = A[row + 1];
    float la = a0 + a1;
    float incl = la;
    #pragma unroll
    for (int off = 1; off < 32; off <<= 1) {
        float o = __shfl_up_sync(0xffffffffu, incl, off);
        if (lane >= off) incl += o;
    }
    float exc = incl - la;
    float p0 = BID[row]     - (exc + a0);
    float p1 = BID[row + 1] - (exc + a0 + a1);

    float m = MSENT, d = 0.f, n[16];
    #pragma unroll
    for (int i = 0; i < 16; i++) n[i] = 0.f;
    sm_step(m, d, n, p0, &g_vg[(size_t)row * 128 + h * 16]);
    sm_step(m, d, n, p1, &g_vg[(size_t)(row + 1) * 128 + h * 16]);

    #pragma unroll
    for (int off = 1; off < 32; off <<= 1) {
        float om, od, on[16];
        WSHFL_STATE(om, od, on, off);
        if (lane >= off) sm_comb(m, d, n, om, od, on);
    }

    g_p0[gl] = p0; g_p1[gl] = p1;
    g_sm[gl] = m;  g_sd[gl] = d;
    #pragma unroll
    for (int i = 0; i < 16; i++) g_sn[i][gl] = n[i];
    if (lane == 31) g_aggA[chunk] = incl;
}

// S2: cross-chunk prefix + replay + gate + z split
__global__ void __launch_bounds__(128) scan_part2(const float* __restrict__ bg) {
    int warp = threadIdx.x >> 5, lane = threadIdx.x & 31;
    int chunk = blockIdx.x * 4 + warp;
    int bh = chunk >> 5, c = chunk & 31;
    int b = bh >> 2, h = bh & 3;
    int row = b * TT + c * 64 + lane * 2;
    int gl = chunk * 32 + lane;

    // --- cross-chunk exclusive prefix (lane l = chunk l of this bh) ---
    float Pm, Pd, Pn[16];
    {
        int cch = bh * 32 + lane;
        float sA = g_aggA[cch];
        int gtop = cch * 32 + 31;
        float m = g_sm[gtop], d = g_sd[gtop], n[16];
        #pragma unroll
        for (int i = 0; i < 16; i++) n[i] = g_sn[i][gtop];

        float cum = sA;
        #pragma unroll
        for (int off = 1; off < 32; off <<= 1) {
            float o = __shfl_up_sync(0xffffffffu, cum, off);
            if (lane >= off) cum += o;
        }
        m -= (cum - sA);                 // -> global frame
        #pragma unroll
        for (int off = 1; off < 32; off <<= 1) {
            float om, od, on[16];
            WSHFL_STATE(om, od, on, off);
            if (lane >= off) sm_comb(m, d, n, om, od, on);
        }
        int src = (c == 0) ? 0 : (c - 1);
        Pm = __shfl_sync(0xffffffffu, m, src);
        Pd = __shfl_sync(0xffffffffu, d, src);
        #pragma unroll
        for (int i = 0; i < 16; i++) Pn[i] = __shfl_sync(0xffffffffu, n[i], src);
        float prefA = __shfl_sync(0xffffffffu, cum, src);
        if (c == 0) {
            Pm = MSENT; Pd = 0.f; prefA = 0.f;
            #pragma unroll
            for (int i = 0; i < 16; i++) Pn[i] = 0.f;
        }
        Pm += prefA;                     // -> this chunk's local frame
    }

    // --- per-lane exclusive state from stored inclusive states ---
    float im = g_sm[gl], id = g_sd[gl], in_[16];
    #pragma unroll
    for (int i = 0; i < 16; i++) in_[i] = g_sn[i][gl];
    float em = __shfl_up_sync(0xffffffffu, im, 1);
    float ed = __shfl_up_sync(0xffffffffu, id, 1);
    float en[16];
    #pragma unroll
    for (int i = 0; i < 16; i++) en[i] = __shfl_up_sync(0xffffffffu, in_[i], 1);
    if (lane == 0) {
        em = MSENT; ed = 0.f;
        #pragma unroll
        for (int i = 0; i < 16; i++) en[i] = 0.f;
    }
    sm_comb(em, ed, en, Pm, Pd, Pn);

    float bgv[16];
    #pragma unroll
    for (int i = 0; i < 16; i++) bgv[i] = bg[h * 16 + i];

    float ps[2] = {g_p0[gl], g_p1[gl]};
    #pragma unroll
    for (int j = 0; j < 2; j++) {
        int r = row + j;
        sm_step(em, ed, en, ps[j], &g_vg[(size_t)r * 128 + h * 16]);
        float inv = __fdividef(1.f, ed);

        const float* gp = &g_vg[(size_t)r * 128 + 64 + h * 16];
        float4 g0 = *(const float4*)&gp[0],  g1 = *(const float4*)&gp[4];
        float4 g2 = *(const float4*)&gp[8],  g3 = *(const float4*)&gp[12];
        float gl16[16] = {g0.x,g0.y,g0.z,g0.w, g1.x,g1.y,g1.z,g1.w,
                          g2.x,g2.y,g2.z,g2.w, g3.x,g3.y,g3.z,g3.w};
        float out[16];
        #pragma unroll
        for (int i = 0; i < 16; i++) {
            float gate = __fdividef(1.f, 1.f + __expf(-(gl16[i] + bgv[i])));
            out[i] = en[i] * inv * gate;
        }
        uint32_t hi[8], lo[8];
        #pragma unroll
        for (int i = 0; i < 8; i++) split2(out[2*i], out[2*i+1], hi[i], lo[i]);
        size_t zb = (size_t)r * 8 + h * 2;
        g_zhi[zb + 0] = make_uint4(hi[0], hi[1], hi[2], hi[3]);
        g_zhi[zb + 1] = make_uint4(hi[4], hi[5], hi[6], hi[7]);
        g_zlo[zb + 0] = make_uint4(lo[0], lo[1], lo[2], lo[3]);
        g_zlo[zb + 1] = make_uint4(lo[4], lo[5], lo[6], lo[7]);
    }
}

// ---------------------------------------------------------------------------
// K5: out = z @ Wo, 512 threads, BM=128, BN=256, grid (2 ntiles, 64 mtiles)
// = 128 CTAs (single wave). Warps 4m x 4n, warp tile 32x64.
// 2-stage pipeline, 48KB/stage: A 16KB | B 32KB. K'=192 (3 chunks).
// ---------------------------------------------------------------------------
__global__ void __launch_bounds__(512) gemm_out_mma(float* __restrict__ O) {
    extern __shared__ __align__(1024) char smem[];
    uint32_t sb = smem_u32(smem);
    int tid = threadIdx.x, wid = tid >> 5, lane = tid & 31;
    int ntile = blockIdx.x, mtile = blockIdx.y;

    const __nv_bfloat16* B = ((const __nv_bfloat16*)g_woT) + (size_t)ntile * 256 * KO;
    size_t aoff = (size_t)mtile * 128 * 64;   // bf16 elements

    int wm = (wid & 3) * 32, wn = (wid >> 2) * 64;
    int lr = lane & 7, sel = lane >> 3;
    int arow = wm + lr + (sel & 1) * 8;
    int acol = (sel >> 1) * 16;
    int brow = wn + lr;
    int bcol = (sel & 1) * 16;

    float acc[2][8][4] = {};

    auto getA = [&](int kc) -> const __nv_bfloat16* {
        return ((kc < 2) ? (const __nv_bfloat16*)g_zhi
                         : (const __nv_bfloat16*)g_zlo) + aoff;   // cast FIRST, then add
    };
    auto load = [&](int kc, int s) {
        uint32_t base = sb + (uint32_t)s * 49152;
        const __nv_bfloat16* Ak = getA(kc);
        const __nv_bfloat16* Bk = B + kc * 64;
        #pragma unroll
        for (int j = 0; j < 2; j++) {              // A: 1024 uint4 (16KB)
            int idx = tid * 2 + j;
            int r = idx >> 3, ch = idx & 7;
            cpa16(base + SWZ((uint32_t)(r * 128 + ch * 16)),
                  Ak + (size_t)r * 64 + ch * 8);
        }
        #pragma unroll
        for (int j = 0; j < 4; j++) {              // B: 2048 uint4 (32KB)
            int idx = j * 512 + tid;
            int r = idx >> 3, ch = idx & 7;
            cpa16(base + 16384 + SWZ((uint32_t)(r * 128 + ch * 16)),
                  Bk + (size_t)r * KO + ch * 8);
        }
        CP_COMMIT();
    };

    load(0, 0);
    for (int kc = 0; kc < 3; kc++) {
        CP_WAIT0();
        __syncthreads();
        if (kc + 1 < 3) load(kc + 1, (kc + 1) & 1);

        uint32_t Ab = sb + (uint32_t)(kc & 1) * 49152;
        uint32_t Bb = Ab + 16384;
        #pragma unroll
        for (int ks = 0; ks < 4; ks++) {
            uint32_t a[2][4], b[8][2];
            #pragma unroll
            for (int mf = 0; mf < 2; mf++) {
                uint32_t addr = Ab + SWZ((uint32_t)((arow + mf * 16) * 128 + acol + ks * 32));
                asm volatile("ldmatrix.sync.aligned.m8n8.x4.shared.b16 {%0,%1,%2,%3}, [%4];"
                    : "=r"(a[mf][0]), "=r"(a[mf][1]), "=r"(a[mf][2]), "=r"(a[mf][3])
                    : "r"(addr));
            }
            #pragma unroll
            for (int nf = 0; nf < 8; nf++) {
                uint32_t addr = Bb + SWZ((uint32_t)((brow + nf * 8) * 128 + bcol + ks * 32));
                asm volatile("ldmatrix.sync.aligned.m8n8.x2.shared.b16 {%0,%1}, [%2];"
                    : "=r"(b[nf][0]), "=r"(b[nf][1])
                    : "r"(addr));
            }
            #pragma unroll
            for (int mf = 0; mf < 2; mf++)
                #pragma unroll
                for (int nf = 0; nf < 8; nf++)
                    mma_bf16(acc[mf][nf], a[mf], b[nf]);
        }
        __syncthreads();
    }

    int er = lane >> 2, ec = (lane & 3) * 2;
    int m0 = mtile * 128, n0 = ntile * 256;

    #pragma unroll
    for (int mf = 0; mf < 2; mf++)
        #pragma unroll
        for (int nf = 0; nf < 8; nf++) {
            int r = m0 + wm + mf * 16 + er;
            int c = n0 + wn + nf * 8 + ec;
            *(float2*)&O[(size_t)r * 512 + c]       = make_float2(acc[mf][nf][0], acc[mf][nf][1]);
            *(float2*)&O[(size_t)(r + 8) * 512 + c] = make_float2(acc[mf][nf][2], acc[mf][nf][3]);
        }
}

// ---------------------------------------------------------------------------
extern "C" void kernel_launch(void* const* d_in, const int* in_sizes, int n_in,
                              void* d_out, int out_size) {
    const float* x  = (const float*)d_in[0];
    const float* Wq = (const float*)d_in[1];
    const float* Wk = (const float*)d_in[2];
    const float* Wv = (const float*)d_in[3];
    const float* Wa = (const float*)d_in[4];
    const float* ba = (const float*)d_in[5];
    const float* Wg = (const float*)d_in[6];
    const float* bg = (const float*)d_in[7];
    const float* Wo = (const float*)d_in[8];
    float* out = (float*)d_out;

    cudaFuncSetAttribute(gemm_qkvg_mma, cudaFuncAttributeMaxDynamicSharedMemorySize, 122880);
    cudaFuncSetAttribute(gemm_out_mma,  cudaFuncAttributeMaxDynamicSharedMemorySize, 98304);

    setup_kernel<<<1664, 256>>>(x, Wa, ba, Wq, Wk, Wv, Wg, Wo);      // #1
    gemm_qkvg_mma<<<128, 512, 122880>>>();                            // #2
    scan_part1<<<128, 128>>>();                                       // #3
    scan_part2<<<128, 128>>>(bg);                                     // #4
    gemm_out_mma<<<dim3(2, 64), 512, 98304>>>(out);                   // #5
}

// round 15
// speedup vs baseline: 1.0062x; 1.0062x over previous
#include <cuda_runtime.h>
#include <cuda_bf16.h>
#include <math.h>
#include <stdint.h>

#define BATCH 4
#define TT 2048
#define DD 512
#define HH 4
#define M_ROWS 8192
#define KQ 1536          // augmented K for qkvg GEMM (hi|hi|lo x hi|lo|hi)
#define KO 192           // augmented K for out GEMM

// ---------------------------------------------------------------------------
// Global scratch (device globals; no allocation allowed)
// ---------------------------------------------------------------------------
__device__ uint4 g_xhi[524288];     // 8MB  [8192][512] bf16
__device__ uint4 g_xlo[524288];     // 8MB
__device__ uint4 g_wcatT[49152];    // 1.5MB [256][1536] bf16 (W_hi|W_lo|W_hi)^T
__device__ uint4 g_zhi[65536];      // 1MB  [8192][64] bf16
__device__ uint4 g_zlo[65536];      // 1MB
__device__ uint4 g_woT[12288];      // 384KB [512][192] bf16 (Wo_hi|Wo_lo|Wo_hi)^T
__device__ float g_vg[M_ROWS*128];  // 4MB  v|g fp32 (cols 0-63 v, 64-127 g)
__device__ float g_a[HH*M_ROWS];    // [h][row]
__device__ float g_bid[HH*M_ROWS];  // [h][row]
// scan intermediates (SoA by global lane id gl = chunk*32 + lane)
__device__ float g_p0[16384], g_p1[16384];
__device__ float g_sm[16384], g_sd[16384];
__device__ float g_sn[16][16384];
__device__ float g_aggA[512];       // per-chunk total sum of a
// compact chunk-top aggregates (coalesced prefix loads in part2)
__device__ float g_topm[512], g_topd[512];
__device__ float g_topn[16][512];

// ---------------------------------------------------------------------------
// Helpers
// ---------------------------------------------------------------------------
__device__ __forceinline__ uint32_t smem_u32(const void* p) {
    uint32_t a;
    asm("{ .reg .u64 t; cvta.to.shared.u64 t, %1; cvt.u32.u64 %0, t; }" : "=r"(a) : "l"(p));
    return a;
}
#define SWZ(x) ((x) ^ (((x) >> 3) & 0x70))

__device__ __forceinline__ void cpa16(uint32_t saddr, const void* g) {
    asm volatile("cp.async.cg.shared.global [%0], [%1], 16;" :: "r"(saddr), "l"(g));
}
#define CP_COMMIT() asm volatile("cp.async.commit_group;" ::: "memory")
#define CP_WAIT0()  asm volatile("cp.async.wait_group 0;" ::: "memory")

__device__ __forceinline__ void mma_bf16(float c[4], const uint32_t a[4], const uint32_t b[2]) {
    asm volatile("mma.sync.aligned.m16n8k16.row.col.f32.bf16.bf16.f32 "
        "{%0,%1,%2,%3}, {%4,%5,%6,%7}, {%8,%9}, {%0,%1,%2,%3};"
        : "+f"(c[0]), "+f"(c[1]), "+f"(c[2]), "+f"(c[3])
        : "r"(a[0]), "r"(a[1]), "r"(a[2]), "r"(a[3]), "r"(b[0]), "r"(b[1]));
}

__device__ __forceinline__ void split2(float a, float b, uint32_t& hi, uint32_t& lo) {
    __nv_bfloat16 ha = __float2bfloat16(a), hb = __float2bfloat16(b);
    float ra = a - __bfloat162float(ha), rb = b - __bfloat162float(hb);
    __nv_bfloat162 H, L;
    H.x = ha; H.y = hb;
    L.x = __float2bfloat16(ra); L.y = __float2bfloat16(rb);
    hi = *reinterpret_cast<uint32_t*>(&H);
    lo = *reinterpret_cast<uint32_t*>(&L);
}

#define MSENT -1e30f

// online-softmax step (inclusive update), branchless
__device__ __forceinline__ void sm_step(float& m, float& d, float n[16],
                                        float p, const float* v) {
    float4 v0 = *(const float4*)&v[0],  v1 = *(const float4*)&v[4];
    float4 v2 = *(const float4*)&v[8],  v3 = *(const float4*)&v[12];
    float vv[16] = {v0.x,v0.y,v0.z,v0.w, v1.x,v1.y,v1.z,v1.w,
                    v2.x,v2.y,v2.z,v2.w, v3.x,v3.y,v3.z,v3.w};
    float M = fmaxf(m, p);
    float sm = __expf(m - M), sp = __expf(p - M);
    d = d * sm + sp;
    #pragma unroll
    for (int i = 0; i < 16; i++) n[i] = n[i] * sm + vv[i] * sp;
    m = M;
}

// state combine: self(right) <- other(left) ⊕ self
__device__ __forceinline__ void sm_comb(float& m, float& d, float n[16],
                                        float om, float od, const float on[16]) {
    float M = fmaxf(om, m);
    float so = __expf(om - M), ss = __expf(m - M);
    d = od * so + d * ss;
    #pragma unroll
    for (int i = 0; i < 16; i++) n[i] = on[i] * so + n[i] * ss;
    m = M;
}

// ---------------------------------------------------------------------------
// K1: merged setup. Blocks [0,1024): x -> (x_hi,x_lo) + a-projection.
//     Blocks [1024,1664): pack weights.
// ---------------------------------------------------------------------------
__global__ void __launch_bounds__(256) setup_kernel(
    const float* __restrict__ X,  const float* __restrict__ Wa,
    const float* __restrict__ ba, const float* __restrict__ Wq,
    const float* __restrict__ Wk, const float* __restrict__ Wv,
    const float* __restrict__ Wg, const float* __restrict__ Wo)
{
    if (blockIdx.x < 1024) {
        int row  = (blockIdx.x * 256 + threadIdx.x) >> 5;
        int lane = threadIdx.x & 31;
        const float* xr = X + (size_t)row * DD;
        int c0 = lane * 16;

        float xv[16];
        #pragma unroll
        for (int i = 0; i < 4; i++) {
            float4 v = *(const float4*)&xr[c0 + i * 4];
            xv[i*4+0] = v.x; xv[i*4+1] = v.y; xv[i*4+2] = v.z; xv[i*4+3] = v.w;
        }

        float4 acc = make_float4(0.f, 0.f, 0.f, 0.f);
        #pragma unroll
        for (int i = 0; i < 16; i++) {
            float4 w = *(const float4*)&Wa[(size_t)(c0 + i) * 4];
            acc.x += xv[i] * w.x; acc.y += xv[i] * w.y;
            acc.z += xv[i] * w.z; acc.w += xv[i] * w.w;
        }

        uint32_t hi[8], lo[8];
        #pragma unroll
        for (int i = 0; i < 8; i++) split2(xv[2*i], xv[2*i+1], hi[i], lo[i]);

        size_t base = (size_t)row * 64 + lane * 2;
        g_xhi[base + 0] = make_uint4(hi[0], hi[1], hi[2], hi[3]);
        g_xhi[base + 1] = make_uint4(hi[4], hi[5], hi[6], hi[7]);
        g_xlo[base + 0] = make_uint4(lo[0], lo[1], lo[2], lo[3]);
        g_xlo[base + 1] = make_uint4(lo[4], lo[5], lo[6], lo[7]);

        #pragma unroll
        for (int off = 16; off > 0; off >>= 1) {
            acc.x += __shfl_down_sync(0xffffffffu, acc.x, off);
            acc.y += __shfl_down_sync(0xffffffffu, acc.y, off);
            acc.z += __shfl_down_sync(0xffffffffu, acc.z, off);
            acc.w += __shfl_down_sync(0xffffffffu, acc.w, off);
        }
        if (lane == 0) {
            float zz[4] = {acc.x + ba[0], acc.y + ba[1], acc.z + ba[2], acc.w + ba[3]};
            #pragma unroll
            for (int h = 0; h < 4; h++) {
                float z = zz[h];
                float sp = fmaxf(z, 0.f) + log1pf(expf(-fabsf(z)));
                g_a[h * M_ROWS + row] = -sp;
            }
        }
    } else {
        int idx = (blockIdx.x - 1024) * 256 + threadIdx.x;
        if (idx < 131072) {
            int k = idx >> 8, n = idx & 255;
            float v;
            if      (n < 64)  v = Wq[k*64 + n];
            else if (n < 128) v = Wk[k*64 + (n-64)];
            else if (n < 192) v = Wv[k*64 + (n-128)];
            else              v = Wg[k*64 + (n-192)];
            __nv_bfloat16 h = __float2bfloat16(v);
            __nv_bfloat16 l = __float2bfloat16(v - __bfloat162float(h));
            __nv_bfloat16* W = (__nv_bfloat16*)g_wcatT;
            W[(size_t)n * KQ +        k] = h;
            W[(size_t)n * KQ +  512 + k] = l;
            W[(size_t)n * KQ + 1024 + k] = h;
        } else {
            int j = idx - 131072;
            int k = j >> 9, n = j & 511;
            float v = Wo[(size_t)k * 512 + n];
            __nv_bfloat16 h = __float2bfloat16(v);
            __nv_bfloat16 l = __float2bfloat16(v - __bfloat162float(h));
            __nv_bfloat16* W = (__nv_bfloat16*)g_woT;
            W[(size_t)n * KO +       k] = h;
            W[(size_t)n * KO +  64 + k] = l;
            W[(size_t)n * KO + 128 + k] = h;
        }
    }
}

// ---------------------------------------------------------------------------
// K2: qkvg GEMM, 512 threads. BM=64, BN=256, grid (128 mtiles) = one wave.
// A read ONCE. Warps 2m x 8n, warp tile 32x32. 3-stage pipeline,
// 40KB/stage: A 8KB | B 32KB. Epilogue: wn<128 -> bid (via smem), else v|g.
// ---------------------------------------------------------------------------
__global__ void __launch_bounds__(512) gemm_qkvg_mma() {
    extern __shared__ __align__(1024) char smem[];
    uint32_t sb = smem_u32(smem);
    int tid = threadIdx.x, wid = tid >> 5, lane = tid & 31;
    int mtile = blockIdx.x;

    const __nv_bfloat16* B = (const __nv_bfloat16*)g_wcatT;   // all 256 n-rows
    size_t aoff = (size_t)mtile * 64 * 512;
    auto getA = [&](int kc) -> const __nv_bfloat16* {
        const __nv_bfloat16* base = (kc < 16) ? (const __nv_bfloat16*)g_xhi
                                              : (const __nv_bfloat16*)g_xlo;
        int kk = (kc < 8) ? kc : ((kc < 16) ? kc - 8 : kc - 16);
        return base + aoff + kk * 64;
    };

    int wm = (wid & 1) * 32, wn = (wid >> 1) * 32;
    int lr = lane & 7, sel = lane >> 3;
    int arow = wm + lr + (sel & 1) * 8;
    int acol = (sel >> 1) * 16;
    int brow = wn + lr;
    int bcol = (sel & 1) * 16;

    float acc[2][4][4] = {};

    auto load = [&](int kc, int s) {
        uint32_t base = sb + (uint32_t)s * 40960;
        const __nv_bfloat16* Ak = getA(kc);
        const __nv_bfloat16* Bk = B + kc * 64;
        {   // A: 64 rows x 64 cols = 512 uint4, 1 per thread
            int r = tid >> 3, ch = tid & 7;
            cpa16(base + SWZ((uint32_t)(r * 128 + ch * 16)),
                  Ak + (size_t)r * 512 + ch * 8);
        }
        #pragma unroll
        for (int j = 0; j < 4; j++) {   // B: 256 rows x 64 cols = 2048 uint4
            int idx = j * 512 + tid;
            int r = idx >> 3, ch = idx & 7;
            cpa16(base + 8192 + SWZ((uint32_t)(r * 128 + ch * 16)),
                  Bk + (size_t)r * KQ + ch * 8);
        }
        CP_COMMIT();
    };

    load(0, 0);
    load(1, 1);

    for (int kc = 0; kc < 24; kc++) {
        asm volatile("cp.async.wait_group 1;" ::: "memory");
        __syncthreads();
        if (kc + 2 < 24) load(kc + 2, (kc + 2) % 3); else CP_COMMIT();

        uint32_t Ab = sb + (uint32_t)(kc % 3) * 40960;
        uint32_t Bb = Ab + 8192;
        #pragma unroll
        for (int ks = 0; ks < 4; ks++) {
            uint32_t a[2][4], b[4][2];
            #pragma unroll
            for (int mf = 0; mf < 2; mf++) {
                uint32_t addr = Ab + SWZ((uint32_t)((arow + mf * 16) * 128 + acol + ks * 32));
                asm volatile("ldmatrix.sync.aligned.m8n8.x4.shared.b16 {%0,%1,%2,%3}, [%4];"
                    : "=r"(a[mf][0]), "=r"(a[mf][1]), "=r"(a[mf][2]), "=r"(a[mf][3])
                    : "r"(addr));
            }
            #pragma unroll
            for (int nf = 0; nf < 4; nf++) {
                uint32_t addr = Bb + SWZ((uint32_t)((brow + nf * 8) * 128 + bcol + ks * 32));
                asm volatile("ldmatrix.sync.aligned.m8n8.x2.shared.b16 {%0,%1}, [%2];"
                    : "=r"(b[nf][0]), "=r"(b[nf][1])
                    : "r"(addr));
            }
            #pragma unroll
            for (int mf = 0; mf < 2; mf++)
                #pragma unroll
                for (int nf = 0; nf < 4; nf++)
                    mma_bf16(acc[mf][nf], a[mf], b[nf]);
        }
    }
    CP_WAIT0();

    int er = lane >> 2, ec = (lane & 3) * 2;
    int m0 = mtile * 64;

    __syncthreads();                       // mainloop smem free
    float* S = (float*)smem;               // 64x128 fp32 = 32KB, xor-swizzled

    if (wn < 128) {
        int xm = er << 4;
        #pragma unroll
        for (int mf = 0; mf < 2; mf++)
            #pragma unroll
            for (int nf = 0; nf < 4; nf++) {
                int r = wm + mf * 16 + er;
                int c = (wn + nf * 8 + ec) ^ xm;
                *(float2*)&S[r * 128 + c]       = make_float2(acc[mf][nf][0], acc[mf][nf][1]);
                *(float2*)&S[(r + 8) * 128 + c] = make_float2(acc[mf][nf][2], acc[mf][nf][3]);
            }
    } else {
        #pragma unroll
        for (int mf = 0; mf < 2; mf++)
            #pragma unroll
            for (int nf = 0; nf < 4; nf++) {
                int r = m0 + wm + mf * 16 + er;
                int c = (wn - 128) + nf * 8 + ec;
                *(float2*)&g_vg[(size_t)r * 128 + c]       = make_float2(acc[mf][nf][0], acc[mf][nf][1]);
                *(float2*)&g_vg[(size_t)(r + 8) * 128 + c] = make_float2(acc[mf][nf][2], acc[mf][nf][3]);
            }
    }
    __syncthreads();

    if (tid < 256) {
        int m = tid >> 2, h = tid & 3;     // 64 rows x 4 heads
        int x = (m & 7) << 4;
        const float* q = &S[m * 128 + ((h * 16) ^ x)];
        const float* k = &S[m * 128 + ((64 + h * 16) ^ x)];
        float s = 0.f;
        #pragma unroll
        for (int i = 0; i < 16; i++) s += q[i] * k[i];
        g_bid[(size_t)h * M_ROWS + m0 + m] = s * 0.25f;
    }
}

// ---------------------------------------------------------------------------
// Scan: 512 chunks (16 bh x 32 chunks of 64 steps), 1 warp per chunk.
// ---------------------------------------------------------------------------
#define WSHFL_STATE(om, od, on, off)                                        \
    do {                                                                    \
        om = __shfl_up_sync(0xffffffffu, m, off);                           \
        od = __shfl_up_sync(0xffffffffu, d, off);                           \
        _Pragma("unroll")                                                   \
        for (int _i = 0; _i < 16; _i++)                                     \
            on[_i] = __shfl_up_sync(0xffffffffu, n[_i], off);               \
    } while (0)

// S1: per-chunk local scan; stores p, per-lane inclusive states, chunk tops
__global__ void __launch_bounds__(128) scan_part1() {
    int warp = threadIdx.x >> 5, lane = threadIdx.x & 31;
    int chunk = blockIdx.x * 4 + warp;
    int bh = chunk >> 5, c = chunk & 31;
    int b = bh >> 2, h = bh & 3;
    int row = b * TT + c * 64 + lane * 2;
    int gl = chunk * 32 + lane;

    const float* A   = g_a   + (size_t)h * M_ROWS;
    const float* BID = g_bid + (size_t)h * M_ROWS;
    float a0 = A[row], a1 = A[row + 1];
    float la = a0 + a1;
    float incl = la;
    #pragma unroll
    for (int off = 1; off < 32; off <<= 1) {
        float o = __shfl_up_sync(0xffffffffu, incl, off);
        if (lane >= off) incl += o;
    }
    float exc = incl - la;
    float p0 = BID[row]     - (exc + a0);
    float p1 = BID[row + 1] - (exc + a0 + a1);

    float m = MSENT, d = 0.f, n[16];
    #pragma unroll
    for (int i = 0; i < 16; i++) n[i] = 0.f;
    sm_step(m, d, n, p0, &g_vg[(size_t)row * 128 + h * 16]);
    sm_step(m, d, n, p1, &g_vg[(size_t)(row + 1) * 128 + h * 16]);

    #pragma unroll
    for (int off = 1; off < 32; off <<= 1) {
        float om, od, on[16];
        WSHFL_STATE(om, od, on, off);
        if (lane >= off) sm_comb(m, d, n, om, od, on);
    }

    g_p0[gl] = p0; g_p1[gl] = p1;
    g_sm[gl] = m;  g_sd[gl] = d;
    #pragma unroll
    for (int i = 0; i < 16; i++) g_sn[i][gl] = n[i];
    if (lane == 31) {
        g_aggA[chunk] = incl;
        g_topm[chunk] = m; g_topd[chunk] = d;
        #pragma unroll
        for (int i = 0; i < 16; i++) g_topn[i][chunk] = n[i];
    }
}

// S2: block-shared cross-chunk prefix (warp 0, coalesced) + replay + gate + z
__global__ void __launch_bounds__(128) scan_part2(const float* __restrict__ bg) {
    __shared__ float sInc[32][20];   // inclusive global-frame states + cumA

    int warp = threadIdx.x >> 5, lane = threadIdx.x & 31;
    int chunk = blockIdx.x * 4 + warp;
    int bh = chunk >> 5, c = chunk & 31;
    int b = bh >> 2, h = bh & 3;
    int row = b * TT + c * 64 + lane * 2;
    int gl = chunk * 32 + lane;

    // --- warp 0: bh-wide inclusive prefix over chunk tops (ONCE per block) ---
    if (warp == 0) {
        int cch = bh * 32 + lane;                 // all 4 chunks share bh
        float sA = g_aggA[cch];
        float m = g_topm[cch], d = g_topd[cch], n[16];
        #pragma unroll
        for (int i = 0; i < 16; i++) n[i] = g_topn[i][cch];   // coalesced

        float cum = sA;
        #pragma unroll
        for (int off = 1; off < 32; off <<= 1) {
            float o = __shfl_up_sync(0xffffffffu, cum, off);
            if (lane >= off) cum += o;
        }
        m -= (cum - sA);                          // -> global frame
        #pragma unroll
        for (int off = 1; off < 32; off <<= 1) {
            float om, od, on[16];
            WSHFL_STATE(om, od, on, off);
            if (lane >= off) sm_comb(m, d, n, om, od, on);
        }
        sInc[lane][0] = m; sInc[lane][1] = d;
        #pragma unroll
        for (int i = 0; i < 16; i++) sInc[lane][2 + i] = n[i];
        sInc[lane][18] = cum;
    }

    // --- per-lane exclusive state from stored inclusive states (overlaps) ---
    float im = g_sm[gl], id = g_sd[gl], in_[16];
    #pragma unroll
    for (int i = 0; i < 16; i++) in_[i] = g_sn[i][gl];
    float em = __shfl_up_sync(0xffffffffu, im, 1);
    float ed = __shfl_up_sync(0xffffffffu, id, 1);
    float en[16];
    #pragma unroll
    for (int i = 0; i < 16; i++) en[i] = __shfl_up_sync(0xffffffffu, in_[i], 1);
    if (lane == 0) {
        em = MSENT; ed = 0.f;
        #pragma unroll
        for (int i = 0; i < 16; i++) en[i] = 0.f;
    }

    __syncthreads();

    // --- pick this chunk's exclusive prefix (chunk-local frame) ---
    float Pm, Pd, Pn[16];
    if (c == 0) {
        Pm = MSENT; Pd = 0.f;
        #pragma unroll
        for (int i = 0; i < 16; i++) Pn[i] = 0.f;
    } else {
        Pm = sInc[c - 1][0] + sInc[c - 1][18];    // + prefA -> local frame
        Pd = sInc[c - 1][1];
        #pragma unroll
        for (int i = 0; i < 16; i++) Pn[i] = sInc[c - 1][2 + i];
    }
    sm_comb(em, ed, en, Pm, Pd, Pn);

    float bgv[16];
    #pragma unroll
    for (int i = 0; i < 16; i++) bgv[i] = bg[h * 16 + i];

    float ps[2] = {g_p0[gl], g_p1[gl]};
    #pragma unroll
    for (int j = 0; j < 2; j++) {
        int r = row + j;
        sm_step(em, ed, en, ps[j], &g_vg[(size_t)r * 128 + h * 16]);
        float inv = __fdividef(1.f, ed);

        const float* gp = &g_vg[(size_t)r * 128 + 64 + h * 16];
        float4 g0 = *(const float4*)&gp[0],  g1 = *(const float4*)&gp[4];
        float4 g2 = *(const float4*)&gp[8],  g3 = *(const float4*)&gp[12];
        float gl16[16] = {g0.x,g0.y,g0.z,g0.w, g1.x,g1.y,g1.z,g1.w,
                          g2.x,g2.y,g2.z,g2.w, g3.x,g3.y,g3.z,g3.w};
        float out[16];
        #pragma unroll
        for (int i = 0; i < 16; i++) {
            float gate = __fdividef(1.f, 1.f + __expf(-(gl16[i] + bgv[i])));
            out[i] = en[i] * inv * gate;
        }
        uint32_t hi[8], lo[8];
        #pragma unroll
        for (int i = 0; i < 8; i++) split2(out[2*i], out[2*i+1], hi[i], lo[i]);
        size_t zb = (size_t)r * 8 + h * 2;
        g_zhi[zb + 0] = make_uint4(hi[0], hi[1], hi[2], hi[3]);
        g_zhi[zb + 1] = make_uint4(hi[4], hi[5], hi[6], hi[7]);
        g_zlo[zb + 0] = make_uint4(lo[0], lo[1], lo[2], lo[3]);
        g_zlo[zb + 1] = make_uint4(lo[4], lo[5], lo[6], lo[7]);
    }
}

// ---------------------------------------------------------------------------
// K5: out = z @ Wo, 512 threads, BM=128, BN=256, grid (2 ntiles, 64 mtiles)
// = 128 CTAs (single wave). Warps 4m x 4n, warp tile 32x64.
// 2-stage pipeline, 48KB/stage: A 16KB | B 32KB. K'=192 (3 chunks).
// ---------------------------------------------------------------------------
__global__ void __launch_bounds__(512) gemm_out_mma(float* __restrict__ O) {
    extern __shared__ __align__(1024) char smem[];
    uint32_t sb = smem_u32(smem);
    int tid = threadIdx.x, wid = tid >> 5, lane = tid & 31;
    int ntile = blockIdx.x, mtile = blockIdx.y;

    const __nv_bfloat16* B = ((const __nv_bfloat16*)g_woT) + (size_t)ntile * 256 * KO;
    size_t aoff = (size_t)mtile * 128 * 64;   // bf16 elements

    int wm = (wid & 3) * 32, wn = (wid >> 2) * 64;
    int lr = lane & 7, sel = lane >> 3;
    int arow = wm + lr + (sel & 1) * 8;
    int acol = (sel >> 1) * 16;
    int brow = wn + lr;
    int bcol = (sel & 1) * 16;

    float acc[2][8][4] = {};

    auto getA = [&](int kc) -> const __nv_bfloat16* {
        return ((kc < 2) ? (const __nv_bfloat16*)g_zhi
                         : (const __nv_bfloat16*)g_zlo) + aoff;   // cast FIRST, then add
    };
    auto load = [&](int kc, int s) {
        uint32_t base = sb + (uint32_t)s * 49152;
        const __nv_bfloat16* Ak = getA(kc);
        const __nv_bfloat16* Bk = B + kc * 64;
        #pragma unroll
        for (int j = 0; j < 2; j++) {              // A: 1024 uint4 (16KB)
            int idx = tid * 2 + j;
            int r = idx >> 3, ch = idx & 7;
            cpa16(base + SWZ((uint32_t)(r * 128 + ch * 16)),
                  Ak + (size_t)r * 64 + ch * 8);
        }
        #pragma unroll
        for (int j = 0; j < 4; j++) {              // B: 2048 uint4 (32KB)
            int idx = j * 512 + tid;
            int r = idx >> 3, ch = idx & 7;
            cpa16(base + 16384 + SWZ((uint32_t)(r * 128 + ch * 16)),
                  Bk + (size_t)r * KO + ch * 8);
        }
        CP_COMMIT();
    };

    load(0, 0);
    for (int kc = 0; kc < 3; kc++) {
        CP_WAIT0();
        __syncthreads();
        if (kc + 1 < 3) load(kc + 1, (kc + 1) & 1);

        uint32_t Ab = sb + (uint32_t)(kc & 1) * 49152;
        uint32_t Bb = Ab + 16384;
        #pragma unroll
        for (int ks = 0; ks < 4; ks++) {
            uint32_t a[2][4], b[8][2];
            #pragma unroll
            for (int mf = 0; mf < 2; mf++) {
                uint32_t addr = Ab + SWZ((uint32_t)((arow + mf * 16) * 128 + acol + ks * 32));
                asm volatile("ldmatrix.sync.aligned.m8n8.x4.shared.b16 {%0,%1,%2,%3}, [%4];"
                    : "=r"(a[mf][0]), "=r"(a[mf][1]), "=r"(a[mf][2]), "=r"(a[mf][3])
                    : "r"(addr));
            }
            #pragma unroll
            for (int nf = 0; nf < 8; nf++) {
                uint32_t addr = Bb + SWZ((uint32_t)((brow + nf * 8) * 128 + bcol + ks * 32));
                asm volatile("ldmatrix.sync.aligned.m8n8.x2.shared.b16 {%0,%1}, [%2];"
                    : "=r"(b[nf][0]), "=r"(b[nf][1])
                    : "r"(addr));
            }
            #pragma unroll
            for (int mf = 0; mf < 2; mf++)
                #pragma unroll
                for (int nf = 0; nf < 8; nf++)
                    mma_bf16(acc[mf][nf], a[mf], b[nf]);
        }
        __syncthreads();
    }

    int er = lane >> 2, ec = (lane & 3) * 2;
    int m0 = mtile * 128, n0 = ntile * 256;

    #pragma unroll
    for (int mf = 0; mf < 2; mf++)
        #pragma unroll
        for (int nf = 0; nf < 8; nf++) {
            int r = m0 + wm + mf * 16 + er;
            int c = n0 + wn + nf * 8 + ec;
            *(float2*)&O[(size_t)r * 512 + c]       = make_float2(acc[mf][nf][0], acc[mf][nf][1]);
            *(float2*)&O[(size_t)(r + 8) * 512 + c] = make_float2(acc[mf][nf][2], acc[mf][nf][3]);
        }
}

// ---------------------------------------------------------------------------
extern "C" void kernel_launch(void* const* d_in, const int* in_sizes, int n_in,
                              void* d_out, int out_size) {
    const float* x  = (const float*)d_in[0];
    const float* Wq = (const float*)d_in[1];
    const float* Wk = (const float*)d_in[2];
    const float* Wv = (const float*)d_in[3];
    const float* Wa = (const float*)d_in[4];
    const float* ba = (const float*)d_in[5];
    const float* Wg = (const float*)d_in[6];
    const float* bg = (const float*)d_in[7];
    const float* Wo = (const float*)d_in[8];
    float* out = (float*)d_out;

    cudaFuncSetAttribute(gemm_qkvg_mma, cudaFuncAttributeMaxDynamicSharedMemorySize, 122880);
    cudaFuncSetAttribute(gemm_out_mma,  cudaFuncAttributeMaxDynamicSharedMemorySize, 98304);

    setup_kernel<<<1664, 256>>>(x, Wa, ba, Wq, Wk, Wv, Wg, Wo);      // #1
    gemm_qkvg_mma<<<128, 512, 122880>>>();                            // #2
    scan_part1<<<128, 128>>>();                                       // #3
    scan_part2<<<128, 128>>>(bg);                                     // #4
    gemm_out_mma<<<dim3(2, 64), 512, 98304>>>(out);                   // #5
}

// round 16
// speedup vs baseline: 1.0259x; 1.0196x over previous
#include <cuda_runtime.h>
#include <cuda_bf16.h>
#include <math.h>
#include <stdint.h>

#define BATCH 4
#define TT 2048
#define DD 512
#define HH 4
#define M_ROWS 8192
#define KQ 1536          // augmented K for qkvg GEMM (hi|hi|lo x hi|lo|hi)
#define KO 192           // augmented K for out GEMM

// ---------------------------------------------------------------------------
// Global scratch (device globals; no allocation allowed)
// ---------------------------------------------------------------------------
__device__ uint4 g_xhi[524288];     // 8MB  [8192][512] bf16
__device__ uint4 g_xlo[524288];     // 8MB
__device__ uint4 g_wcatT[49152];    // 1.5MB [256][1536] bf16 (W_hi|W_lo|W_hi)^T
__device__ uint4 g_zhi[65536];      // 1MB  [8192][64] bf16
__device__ uint4 g_zlo[65536];      // 1MB
__device__ uint4 g_woT[12288];      // 384KB [512][192] bf16 (Wo_hi|Wo_lo|Wo_hi)^T
__device__ float g_vg[M_ROWS*128];  // 4MB  v|g fp32 (cols 0-63 v, 64-127 g)
__device__ float g_a[HH*M_ROWS];    // [h][row]
__device__ float g_bid[HH*M_ROWS];  // [h][row]
// cross-chunk aggregates (coalesced)
__device__ float g_aggA[512];
__device__ float g_topm[512], g_topd[512];
__device__ float g_topn[16][512];
__device__ int   g_bar;             // grid barrier counter (reset by setup)

// ---------------------------------------------------------------------------
// Helpers
// ---------------------------------------------------------------------------
__device__ __forceinline__ uint32_t smem_u32(const void* p) {
    uint32_t a;
    asm("{ .reg .u64 t; cvta.to.shared.u64 t, %1; cvt.u32.u64 %0, t; }" : "=r"(a) : "l"(p));
    return a;
}
#define SWZ(x) ((x) ^ (((x) >> 3) & 0x70))

__device__ __forceinline__ void cpa16(uint32_t saddr, const void* g) {
    asm volatile("cp.async.cg.shared.global [%0], [%1], 16;" :: "r"(saddr), "l"(g));
}
#define CP_COMMIT() asm volatile("cp.async.commit_group;" ::: "memory")
#define CP_WAIT0()  asm volatile("cp.async.wait_group 0;" ::: "memory")

__device__ __forceinline__ void mma_bf16(float c[4], const uint32_t a[4], const uint32_t b[2]) {
    asm volatile("mma.sync.aligned.m16n8k16.row.col.f32.bf16.bf16.f32 "
        "{%0,%1,%2,%3}, {%4,%5,%6,%7}, {%8,%9}, {%0,%1,%2,%3};"
        : "+f"(c[0]), "+f"(c[1]), "+f"(c[2]), "+f"(c[3])
        : "r"(a[0]), "r"(a[1]), "r"(a[2]), "r"(a[3]), "r"(b[0]), "r"(b[1]));
}

__device__ __forceinline__ void split2(float a, float b, uint32_t& hi, uint32_t& lo) {
    __nv_bfloat16 ha = __float2bfloat16(a), hb = __float2bfloat16(b);
    float ra = a - __bfloat162float(ha), rb = b - __bfloat162float(hb);
    __nv_bfloat162 H, L;
    H.x = ha; H.y = hb;
    L.x = __float2bfloat16(ra); L.y = __float2bfloat16(rb);
    hi = *reinterpret_cast<uint32_t*>(&H);
    lo = *reinterpret_cast<uint32_t*>(&L);
}

#define MSENT -1e30f

// online-softmax step with register-resident v
__device__ __forceinline__ void sm_step_r(float& m, float& d, float n[16],
                                          float p, const float vv[16]) {
    float M = fmaxf(m, p);
    float sm = __expf(m - M), sp = __expf(p - M);
    d = d * sm + sp;
    #pragma unroll
    for (int i = 0; i < 16; i++) n[i] = n[i] * sm + vv[i] * sp;
    m = M;
}

// state combine: self(right) <- other(left) ⊕ self
__device__ __forceinline__ void sm_comb(float& m, float& d, float n[16],
                                        float om, float od, const float on[16]) {
    float M = fmaxf(om, m);
    float so = __expf(om - M), ss = __expf(m - M);
    d = od * so + d * ss;
    #pragma unroll
    for (int i = 0; i < 16; i++) n[i] = on[i] * so + n[i] * ss;
    m = M;
}

#define WSHFL_STATE(om, od, on, off)                                        \
    do {                                                                    \
        om = __shfl_up_sync(0xffffffffu, m, off);                           \
        od = __shfl_up_sync(0xffffffffu, d, off);                           \
        _Pragma("unroll")                                                   \
        for (int _i = 0; _i < 16; _i++)                                     \
            on[_i] = __shfl_up_sync(0xffffffffu, n[_i], off);               \
    } while (0)

// ---------------------------------------------------------------------------
// K1: merged setup. Blocks [0,1024): x -> (x_hi,x_lo) + a-projection.
//     Blocks [1024,1664): pack weights. Also resets the grid barrier.
// ---------------------------------------------------------------------------
__global__ void __launch_bounds__(256) setup_kernel(
    const float* __restrict__ X,  const float* __restrict__ Wa,
    const float* __restrict__ ba, const float* __restrict__ Wq,
    const float* __restrict__ Wk, const float* __restrict__ Wv,
    const float* __restrict__ Wg, const float* __restrict__ Wo)
{
    if (blockIdx.x == 0 && threadIdx.x == 0) g_bar = 0;

    if (blockIdx.x < 1024) {
        int row  = (blockIdx.x * 256 + threadIdx.x) >> 5;
        int lane = threadIdx.x & 31;
        const float* xr = X + (size_t)row * DD;
        int c0 = lane * 16;

        float xv[16];
        #pragma unroll
        for (int i = 0; i < 4; i++) {
            float4 v = *(const float4*)&xr[c0 + i * 4];
            xv[i*4+0] = v.x; xv[i*4+1] = v.y; xv[i*4+2] = v.z; xv[i*4+3] = v.w;
        }

        float4 acc = make_float4(0.f, 0.f, 0.f, 0.f);
        #pragma unroll
        for (int i = 0; i < 16; i++) {
            float4 w = *(const float4*)&Wa[(size_t)(c0 + i) * 4];
            acc.x += xv[i] * w.x; acc.y += xv[i] * w.y;
            acc.z += xv[i] * w.z; acc.w += xv[i] * w.w;
        }

        uint32_t hi[8], lo[8];
        #pragma unroll
        for (int i = 0; i < 8; i++) split2(xv[2*i], xv[2*i+1], hi[i], lo[i]);

        size_t base = (size_t)row * 64 + lane * 2;
        g_xhi[base + 0] = make_uint4(hi[0], hi[1], hi[2], hi[3]);
        g_xhi[base + 1] = make_uint4(hi[4], hi[5], hi[6], hi[7]);
        g_xlo[base + 0] = make_uint4(lo[0], lo[1], lo[2], lo[3]);
        g_xlo[base + 1] = make_uint4(lo[4], lo[5], lo[6], lo[7]);

        #pragma unroll
        for (int off = 16; off > 0; off >>= 1) {
            acc.x += __shfl_down_sync(0xffffffffu, acc.x, off);
            acc.y += __shfl_down_sync(0xffffffffu, acc.y, off);
            acc.z += __shfl_down_sync(0xffffffffu, acc.z, off);
            acc.w += __shfl_down_sync(0xffffffffu, acc.w, off);
        }
        if (lane == 0) {
            float zz[4] = {acc.x + ba[0], acc.y + ba[1], acc.z + ba[2], acc.w + ba[3]};
            #pragma unroll
            for (int h = 0; h < 4; h++) {
                float z = zz[h];
                float sp = fmaxf(z, 0.f) + log1pf(expf(-fabsf(z)));
                g_a[h * M_ROWS + row] = -sp;
            }
        }
    } else {
        int idx = (blockIdx.x - 1024) * 256 + threadIdx.x;
        if (idx < 131072) {
            int k = idx >> 8, n = idx & 255;
            float v;
            if      (n < 64)  v = Wq[k*64 + n];
            else if (n < 128) v = Wk[k*64 + (n-64)];
            else if (n < 192) v = Wv[k*64 + (n-128)];
            else              v = Wg[k*64 + (n-192)];
            __nv_bfloat16 h = __float2bfloat16(v);
            __nv_bfloat16 l = __float2bfloat16(v - __bfloat162float(h));
            __nv_bfloat16* W = (__nv_bfloat16*)g_wcatT;
            W[(size_t)n * KQ +        k] = h;
            W[(size_t)n * KQ +  512 + k] = l;
            W[(size_t)n * KQ + 1024 + k] = h;
        } else {
            int j = idx - 131072;
            int k = j >> 9, n = j & 511;
            float v = Wo[(size_t)k * 512 + n];
            __nv_bfloat16 h = __float2bfloat16(v);
            __nv_bfloat16 l = __float2bfloat16(v - __bfloat162float(h));
            __nv_bfloat16* W = (__nv_bfloat16*)g_woT;
            W[(size_t)n * KO +       k] = h;
            W[(size_t)n * KO +  64 + k] = l;
            W[(size_t)n * KO + 128 + k] = h;
        }
    }
}

// ---------------------------------------------------------------------------
// K2: qkvg GEMM, 512 threads. BM=64, BN=256, grid (128 mtiles) = one wave.
// A read ONCE. Warps 2m x 8n, warp tile 32x32. 3-stage pipeline,
// 40KB/stage: A 8KB | B 32KB. Epilogue: wn<128 -> bid (via smem), else v|g.
// ---------------------------------------------------------------------------
__global__ void __launch_bounds__(512) gemm_qkvg_mma() {
    extern __shared__ __align__(1024) char smem[];
    uint32_t sb = smem_u32(smem);
    int tid = threadIdx.x, wid = tid >> 5, lane = tid & 31;
    int mtile = blockIdx.x;

    const __nv_bfloat16* B = (const __nv_bfloat16*)g_wcatT;   // all 256 n-rows
    size_t aoff = (size_t)mtile * 64 * 512;
    auto getA = [&](int kc) -> const __nv_bfloat16* {
        const __nv_bfloat16* base = (kc < 16) ? (const __nv_bfloat16*)g_xhi
                                              : (const __nv_bfloat16*)g_xlo;
        int kk = (kc < 8) ? kc : ((kc < 16) ? kc - 8 : kc - 16);
        return base + aoff + kk * 64;
    };

    int wm = (wid & 1) * 32, wn = (wid >> 1) * 32;
    int lr = lane & 7, sel = lane >> 3;
    int arow = wm + lr + (sel & 1) * 8;
    int acol = (sel >> 1) * 16;
    int brow = wn + lr;
    int bcol = (sel & 1) * 16;

    float acc[2][4][4] = {};

    auto load = [&](int kc, int s) {
        uint32_t base = sb + (uint32_t)s * 40960;
        const __nv_bfloat16* Ak = getA(kc);
        const __nv_bfloat16* Bk = B + kc * 64;
        {   // A: 64 rows x 64 cols = 512 uint4, 1 per thread
            int r = tid >> 3, ch = tid & 7;
            cpa16(base + SWZ((uint32_t)(r * 128 + ch * 16)),
                  Ak + (size_t)r * 512 + ch * 8);
        }
        #pragma unroll
        for (int j = 0; j < 4; j++) {   // B: 256 rows x 64 cols = 2048 uint4
            int idx = j * 512 + tid;
            int r = idx >> 3, ch = idx & 7;
            cpa16(base + 8192 + SWZ((uint32_t)(r * 128 + ch * 16)),
                  Bk + (size_t)r * KQ + ch * 8);
        }
        CP_COMMIT();
    };

    load(0, 0);
    load(1, 1);

    for (int kc = 0; kc < 24; kc++) {
        asm volatile("cp.async.wait_group 1;" ::: "memory");
        __syncthreads();
        if (kc + 2 < 24) load(kc + 2, (kc + 2) % 3); else CP_COMMIT();

        uint32_t Ab = sb + (uint32_t)(kc % 3) * 40960;
        uint32_t Bb = Ab + 8192;
        #pragma unroll
        for (int ks = 0; ks < 4; ks++) {
            uint32_t a[2][4], b[4][2];
            #pragma unroll
            for (int mf = 0; mf < 2; mf++) {
                uint32_t addr = Ab + SWZ((uint32_t)((arow + mf * 16) * 128 + acol + ks * 32));
                asm volatile("ldmatrix.sync.aligned.m8n8.x4.shared.b16 {%0,%1,%2,%3}, [%4];"
                    : "=r"(a[mf][0]), "=r"(a[mf][1]), "=r"(a[mf][2]), "=r"(a[mf][3])
                    : "r"(addr));
            }
            #pragma unroll
            for (int nf = 0; nf < 4; nf++) {
                uint32_t addr = Bb + SWZ((uint32_t)((brow + nf * 8) * 128 + bcol + ks * 32));
                asm volatile("ldmatrix.sync.aligned.m8n8.x2.shared.b16 {%0,%1}, [%2];"
                    : "=r"(b[nf][0]), "=r"(b[nf][1])
                    : "r"(addr));
            }
            #pragma unroll
            for (int mf = 0; mf < 2; mf++)
                #pragma unroll
                for (int nf = 0; nf < 4; nf++)
                    mma_bf16(acc[mf][nf], a[mf], b[nf]);
        }
    }
    CP_WAIT0();

    int er = lane >> 2, ec = (lane & 3) * 2;
    int m0 = mtile * 64;

    __syncthreads();                       // mainloop smem free
    float* S = (float*)smem;               // 64x128 fp32 = 32KB, xor-swizzled

    if (wn < 128) {
        int xm = er << 4;
        #pragma unroll
        for (int mf = 0; mf < 2; mf++)
            #pragma unroll
            for (int nf = 0; nf < 4; nf++) {
                int r = wm + mf * 16 + er;
                int c = (wn + nf * 8 + ec) ^ xm;
                *(float2*)&S[r * 128 + c]       = make_float2(acc[mf][nf][0], acc[mf][nf][1]);
                *(float2*)&S[(r + 8) * 128 + c] = make_float2(acc[mf][nf][2], acc[mf][nf][3]);
            }
    } else {
        #pragma unroll
        for (int mf = 0; mf < 2; mf++)
            #pragma unroll
            for (int nf = 0; nf < 4; nf++) {
                int r = m0 + wm + mf * 16 + er;
                int c = (wn - 128) + nf * 8 + ec;
                *(float2*)&g_vg[(size_t)r * 128 + c]       = make_float2(acc[mf][nf][0], acc[mf][nf][1]);
                *(float2*)&g_vg[(size_t)(r + 8) * 128 + c] = make_float2(acc[mf][nf][2], acc[mf][nf][3]);
            }
    }
    __syncthreads();

    if (tid < 256) {
        int m = tid >> 2, h = tid & 3;     // 64 rows x 4 heads
        int x = (m & 7) << 4;
        const float* q = &S[m * 128 + ((h * 16) ^ x)];
        const float* k = &S[m * 128 + ((64 + h * 16) ^ x)];
        float s = 0.f;
        #pragma unroll
        for (int i = 0; i < 16; i++) s += q[i] * k[i];
        g_bid[(size_t)h * M_ROWS + m0 + m] = s * 0.25f;
    }
}

// ---------------------------------------------------------------------------
// K3: FUSED scan with grid barrier. 128 blocks x 128 threads (4 chunks/block,
// all same bh). Per-lane states, p, and v stay in REGISTERS across the barrier.
// ---------------------------------------------------------------------------
__global__ void __launch_bounds__(128) scan_fused(const float* __restrict__ bg) {
    __shared__ float sInc[32][20];   // inclusive global-frame chunk states + cumA

    int warp = threadIdx.x >> 5, lane = threadIdx.x & 31;
    int chunk = blockIdx.x * 4 + warp;
    int bh = chunk >> 5, c = chunk & 31;
    int b = bh >> 2, h = bh & 3;
    int row = b * TT + c * 64 + lane * 2;

    // ---- Phase 1: local logits + 2-step state + warp inclusive scan ----
    const float* A   = g_a   + (size_t)h * M_ROWS;
    const float* BID = g_bid + (size_t)h * M_ROWS;
    float a0 = A[row], a1 = A[row + 1];
    float la = a0 + a1;
    float incl = la;
    #pragma unroll
    for (int off = 1; off < 32; off <<= 1) {
        float o = __shfl_up_sync(0xffffffffu, incl, off);
        if (lane >= off) incl += o;
    }
    float exc = incl - la;
    float p0 = BID[row]     - (exc + a0);
    float p1 = BID[row + 1] - (exc + a0 + a1);

    float vvA[16], vvB[16];
    {
        const float* v0 = &g_vg[(size_t)row * 128 + h * 16];
        const float* v1 = &g_vg[(size_t)(row + 1) * 128 + h * 16];
        #pragma unroll
        for (int i = 0; i < 4; i++) {
            float4 t0 = *(const float4*)&v0[i * 4];
            float4 t1 = *(const float4*)&v1[i * 4];
            vvA[i*4+0]=t0.x; vvA[i*4+1]=t0.y; vvA[i*4+2]=t0.z; vvA[i*4+3]=t0.w;
            vvB[i*4+0]=t1.x; vvB[i*4+1]=t1.y; vvB[i*4+2]=t1.z; vvB[i*4+3]=t1.w;
        }
    }

    float m = MSENT, d = 0.f, n[16];
    #pragma unroll
    for (int i = 0; i < 16; i++) n[i] = 0.f;
    sm_step_r(m, d, n, p0, vvA);
    sm_step_r(m, d, n, p1, vvB);

    #pragma unroll
    for (int off = 1; off < 32; off <<= 1) {
        float om, od, on[16];
        WSHFL_STATE(om, od, on, off);
        if (lane >= off) sm_comb(m, d, n, om, od, on);
    }

    if (lane == 31) {
        g_aggA[chunk] = incl;
        g_topm[chunk] = m; g_topd[chunk] = d;
        #pragma unroll
        for (int i = 0; i < 16; i++) g_topn[i][chunk] = n[i];
        __threadfence();
    }
    __syncthreads();

    // ---- grid barrier (all 128 blocks co-resident: grid <= #SMs) ----
    if (threadIdx.x == 0) {
        atomicAdd(&g_bar, 1);
        while (*((volatile int*)&g_bar) < (int)gridDim.x) { }
        __threadfence();
    }
    __syncthreads();

    // ---- warp 0: bh-wide inclusive prefix over chunk tops (once/block) ----
    if (warp == 0) {
        int cch = bh * 32 + lane;
        float sA = g_aggA[cch];
        float m = g_topm[cch], d = g_topd[cch], n[16];   // shadows outer
        #pragma unroll
        for (int i = 0; i < 16; i++) n[i] = g_topn[i][cch];

        float cum = sA;
        #pragma unroll
        for (int off = 1; off < 32; off <<= 1) {
            float o = __shfl_up_sync(0xffffffffu, cum, off);
            if (lane >= off) cum += o;
        }
        m -= (cum - sA);                  // -> global frame
        #pragma unroll
        for (int off = 1; off < 32; off <<= 1) {
            float om, od, on[16];
            WSHFL_STATE(om, od, on, off);
            if (lane >= off) sm_comb(m, d, n, om, od, on);
        }
        sInc[lane][0] = m; sInc[lane][1] = d;
        #pragma unroll
        for (int i = 0; i < 16; i++) sInc[lane][2 + i] = n[i];
        sInc[lane][18] = cum;
    }

    // ---- per-lane exclusive from register state ----
    float em = __shfl_up_sync(0xffffffffu, m, 1);
    float ed = __shfl_up_sync(0xffffffffu, d, 1);
    float en[16];
    #pragma unroll
    for (int i = 0; i < 16; i++) en[i] = __shfl_up_sync(0xffffffffu, n[i], 1);
    if (lane == 0) {
        em = MSENT; ed = 0.f;
        #pragma unroll
        for (int i = 0; i < 16; i++) en[i] = 0.f;
    }

    __syncthreads();

    float Pm, Pd, Pn[16];
    if (c == 0) {
        Pm = MSENT; Pd = 0.f;
        #pragma unroll
        for (int i = 0; i < 16; i++) Pn[i] = 0.f;
    } else {
        Pm = sInc[c - 1][0] + sInc[c - 1][18];    // + prefA -> local frame
        Pd = sInc[c - 1][1];
        #pragma unroll
        for (int i = 0; i < 16; i++) Pn[i] = sInc[c - 1][2 + i];
    }
    sm_comb(em, ed, en, Pm, Pd, Pn);

    float bgv[16];
    #pragma unroll
    for (int i = 0; i < 16; i++) bgv[i] = bg[h * 16 + i];

    // ---- replay (v in registers) + gate + z split ----
    #pragma unroll
    for (int j = 0; j < 2; j++) {
        int r = row + j;
        sm_step_r(em, ed, en, (j == 0) ? p0 : p1, (j == 0) ? vvA : vvB);
        float inv = __fdividef(1.f, ed);

        const float* gp = &g_vg[(size_t)r * 128 + 64 + h * 16];
        float4 g0 = *(const float4*)&gp[0],  g1 = *(const float4*)&gp[4];
        float4 g2 = *(const float4*)&gp[8],  g3 = *(const float4*)&gp[12];
        float gl16[16] = {g0.x,g0.y,g0.z,g0.w, g1.x,g1.y,g1.z,g1.w,
                          g2.x,g2.y,g2.z,g2.w, g3.x,g3.y,g3.z,g3.w};
        float out[16];
        #pragma unroll
        for (int i = 0; i < 16; i++) {
            float gate = __fdividef(1.f, 1.f + __expf(-(gl16[i] + bgv[i])));
            out[i] = en[i] * inv * gate;
        }
        uint32_t hi[8], lo[8];
        #pragma unroll
        for (int i = 0; i < 8; i++) split2(out[2*i], out[2*i+1], hi[i], lo[i]);
        size_t zb = (size_t)r * 8 + h * 2;
        g_zhi[zb + 0] = make_uint4(hi[0], hi[1], hi[2], hi[3]);
        g_zhi[zb + 1] = make_uint4(hi[4], hi[5], hi[6], hi[7]);
        g_zlo[zb + 0] = make_uint4(lo[0], lo[1], lo[2], lo[3]);
        g_zlo[zb + 1] = make_uint4(lo[4], lo[5], lo[6], lo[7]);
    }
}

// ---------------------------------------------------------------------------
// K4: out = z @ Wo, 512 threads, BM=128, BN=256, grid (2 ntiles, 64 mtiles)
// = 128 CTAs (single wave). Warps 4m x 4n, warp tile 32x64.
// 2-stage pipeline, 48KB/stage: A 16KB | B 32KB. K'=192 (3 chunks).
// ---------------------------------------------------------------------------
__global__ void __launch_bounds__(512) gemm_out_mma(float* __restrict__ O) {
    extern __shared__ __align__(1024) char smem[];
    uint32_t sb = smem_u32(smem);
    int tid = threadIdx.x, wid = tid >> 5, lane = tid & 31;
    int ntile = blockIdx.x, mtile = blockIdx.y;

    const __nv_bfloat16* B = ((const __nv_bfloat16*)g_woT) + (size_t)ntile * 256 * KO;
    size_t aoff = (size_t)mtile * 128 * 64;   // bf16 elements

    int wm = (wid & 3) * 32, wn = (wid >> 2) * 64;
    int lr = lane & 7, sel = lane >> 3;
    int arow = wm + lr + (sel & 1) * 8;
    int acol = (sel >> 1) * 16;
    int brow = wn + lr;
    int bcol = (sel & 1) * 16;

    float acc[2][8][4] = {};

    auto getA = [&](int kc) -> const __nv_bfloat16* {
        return ((kc < 2) ? (const __nv_bfloat16*)g_zhi
                         : (const __nv_bfloat16*)g_zlo) + aoff;   // cast FIRST, then add
    };
    auto load = [&](int kc, int s) {
        uint32_t base = sb + (uint32_t)s * 49152;
        const __nv_bfloat16* Ak = getA(kc);
        const __nv_bfloat16* Bk = B + kc * 64;
        #pragma unroll
        for (int j = 0; j < 2; j++) {              // A: 1024 uint4 (16KB)
            int idx = tid * 2 + j;
            int r = idx >> 3, ch = idx & 7;
            cpa16(base + SWZ((uint32_t)(r * 128 + ch * 16)),
                  Ak + (size_t)r * 64 + ch * 8);
        }
        #pragma unroll
        for (int j = 0; j < 4; j++) {              // B: 2048 uint4 (32KB)
            int idx = j * 512 + tid;
            int r = idx >> 3, ch = idx & 7;
            cpa16(base + 16384 + SWZ((uint32_t)(r * 128 + ch * 16)),
                  Bk + (size_t)r * KO + ch * 8);
        }
        CP_COMMIT();
    };

    load(0, 0);
    for (int kc = 0; kc < 3; kc++) {
        CP_WAIT0();
        __syncthreads();
        if (kc + 1 < 3) load(kc + 1, (kc + 1) & 1);

        uint32_t Ab = sb + (uint32_t)(kc & 1) * 49152;
        uint32_t Bb = Ab + 16384;
        #pragma unroll
        for (int ks = 0; ks < 4; ks++) {
            uint32_t a[2][4], b[8][2];
            #pragma unroll
            for (int mf = 0; mf < 2; mf++) {
                uint32_t addr = Ab + SWZ((uint32_t)((arow + mf * 16) * 128 + acol + ks * 32));
                asm volatile("ldmatrix.sync.aligned.m8n8.x4.shared.b16 {%0,%1,%2,%3}, [%4];"
                    : "=r"(a[mf][0]), "=r"(a[mf][1]), "=r"(a[mf][2]), "=r"(a[mf][3])
                    : "r"(addr));
            }
            #pragma unroll
            for (int nf = 0; nf < 8; nf++) {
                uint32_t addr = Bb + SWZ((uint32_t)((brow + nf * 8) * 128 + bcol + ks * 32));
                asm volatile("ldmatrix.sync.aligned.m8n8.x2.shared.b16 {%0,%1}, [%2];"
                    : "=r"(b[nf][0]), "=r"(b[nf][1])
                    : "r"(addr));
            }
            #pragma unroll
            for (int mf = 0; mf < 2; mf++)
                #pragma unroll
                for (int nf = 0; nf < 8; nf++)
                    mma_bf16(acc[mf][nf], a[mf], b[nf]);
        }
        __syncthreads();
    }

    int er = lane >> 2, ec = (lane & 3) * 2;
    int m0 = mtile * 128, n0 = ntile * 256;

    #pragma unroll
    for (int mf = 0; mf < 2; mf++)
        #pragma unroll
        for (int nf = 0; nf < 8; nf++) {
            int r = m0 + wm + mf * 16 + er;
            int c = n0 + wn + nf * 8 + ec;
            *(float2*)&O[(size_t)r * 512 + c]       = make_float2(acc[mf][nf][0], acc[mf][nf][1]);
            *(float2*)&O[(size_t)(r + 8) * 512 + c] = make_float2(acc[mf][nf][2], acc[mf][nf][3]);
        }
}

// ---------------------------------------------------------------------------
extern "C" void kernel_launch(void* const* d_in, const int* in_sizes, int n_in,
                              void* d_out, int out_size) {
    const float* x  = (const float*)d_in[0];
    const float* Wq = (const float*)d_in[1];
    const float* Wk = (const float*)d_in[2];
    const float* Wv = (const float*)d_in[3];
    const float* Wa = (const float*)d_in[4];
    const float* ba = (const float*)d_in[5];
    const float* Wg = (const float*)d_in[6];
    const float* bg = (const float*)d_in[7];
    const float* Wo = (const float*)d_in[8];
    float* out = (float*)d_out;

    cudaFuncSetAttribute(gemm_qkvg_mma, cudaFuncAttributeMaxDynamicSharedMemorySize, 122880);
    cudaFuncSetAttribute(gemm_out_mma,  cudaFuncAttributeMaxDynamicSharedMemorySize, 98304);

    setup_kernel<<<1664, 256>>>(x, Wa, ba, Wq, Wk, Wv, Wg, Wo);      // #1
    gemm_qkvg_mma<<<128, 512, 122880>>>();                            // #2
    scan_fused<<<128, 128>>>(bg);                                     // #3
    gemm_out_mma<<<dim3(2, 64), 512, 98304>>>(out);                   // #4
}

// round 17
// speedup vs baseline: 1.0606x; 1.0339x over previous
#include <cuda_runtime.h>
#include <cuda_bf16.h>
#include <math.h>
#include <stdint.h>

#define BATCH 4
#define TT 2048
#define DD 512
#define HH 4
#define M_ROWS 8192
#define KQ 1536          // augmented K for qkvg GEMM (hi|hi|lo x hi|lo|hi)
#define KO 192           // augmented K for out GEMM

// ---------------------------------------------------------------------------
// Global scratch (device globals; no allocation allowed)
// ---------------------------------------------------------------------------
__device__ uint4 g_xhi[524288];     // 8MB  [8192][512] bf16
__device__ uint4 g_xlo[524288];     // 8MB
__device__ uint4 g_wcatT[49152];    // 1.5MB [256][1536] bf16 (W_hi|W_lo|W_hi)^T
__device__ uint4 g_zhi[65536];      // 1MB  [8192][64] bf16
__device__ uint4 g_zlo[65536];      // 1MB
__device__ uint4 g_woT[12288];      // 384KB [512][192] bf16 (Wo_hi|Wo_lo|Wo_hi)^T
__device__ float g_vg[M_ROWS*128];  // 4MB  v|g fp32 (cols 0-63 v, 64-127 g)
__device__ float g_a[HH*M_ROWS];    // [h][row]
__device__ float g_bid[HH*M_ROWS];  // [h][row]
// cross-chunk aggregates (coalesced)
__device__ float g_aggA[512];
__device__ float g_topm[512], g_topd[512];
__device__ float g_topn[16][512];
__device__ int   g_bar;             // grid barrier counter (reset by setup)

// ---------------------------------------------------------------------------
// Helpers
// ---------------------------------------------------------------------------
__device__ __forceinline__ uint32_t smem_u32(const void* p) {
    uint32_t a;
    asm("{ .reg .u64 t; cvta.to.shared.u64 t, %1; cvt.u32.u64 %0, t; }" : "=r"(a) : "l"(p));
    return a;
}
#define SWZ(x) ((x) ^ (((x) >> 3) & 0x70))

__device__ __forceinline__ void cpa16(uint32_t saddr, const void* g) {
    asm volatile("cp.async.cg.shared.global [%0], [%1], 16;" :: "r"(saddr), "l"(g));
}
#define CP_COMMIT() asm volatile("cp.async.commit_group;" ::: "memory")
#define CP_WAIT0()  asm volatile("cp.async.wait_group 0;" ::: "memory")

__device__ __forceinline__ void mma_bf16(float c[4], const uint32_t a[4], const uint32_t b[2]) {
    asm volatile("mma.sync.aligned.m16n8k16.row.col.f32.bf16.bf16.f32 "
        "{%0,%1,%2,%3}, {%4,%5,%6,%7}, {%8,%9}, {%0,%1,%2,%3};"
        : "+f"(c[0]), "+f"(c[1]), "+f"(c[2]), "+f"(c[3])
        : "r"(a[0]), "r"(a[1]), "r"(a[2]), "r"(a[3]), "r"(b[0]), "r"(b[1]));
}

__device__ __forceinline__ void split2(float a, float b, uint32_t& hi, uint32_t& lo) {
    __nv_bfloat16 ha = __float2bfloat16(a), hb = __float2bfloat16(b);
    float ra = a - __bfloat162float(ha), rb = b - __bfloat162float(hb);
    __nv_bfloat162 H, L;
    H.x = ha; H.y = hb;
    L.x = __float2bfloat16(ra); L.y = __float2bfloat16(rb);
    hi = *reinterpret_cast<uint32_t*>(&H);
    lo = *reinterpret_cast<uint32_t*>(&L);
}

#define MSENT -1e30f

// online-softmax step with register-resident v
__device__ __forceinline__ void sm_step_r(float& m, float& d, float n[16],
                                          float p, const float vv[16]) {
    float M = fmaxf(m, p);
    float sm = __expf(m - M), sp = __expf(p - M);
    d = d * sm + sp;
    #pragma unroll
    for (int i = 0; i < 16; i++) n[i] = n[i] * sm + vv[i] * sp;
    m = M;
}

// state combine: self(right) <- other(left) ⊕ self
__device__ __forceinline__ void sm_comb(float& m, float& d, float n[16],
                                        float om, float od, const float on[16]) {
    float M = fmaxf(om, m);
    float so = __expf(om - M), ss = __expf(m - M);
    d = od * so + d * ss;
    #pragma unroll
    for (int i = 0; i < 16; i++) n[i] = on[i] * so + n[i] * ss;
    m = M;
}

#define WSHFL_STATE(om, od, on, off)                                        \
    do {                                                                    \
        om = __shfl_up_sync(0xffffffffu, m, off);                           \
        od = __shfl_up_sync(0xffffffffu, d, off);                           \
        _Pragma("unroll")                                                   \
        for (int _i = 0; _i < 16; _i++)                                     \
            on[_i] = __shfl_up_sync(0xffffffffu, n[_i], off);               \
    } while (0)

// ---------------------------------------------------------------------------
// K1: merged setup. Blocks [0,1024): x -> (x_hi,x_lo) + a-projection.
//     Blocks [1024,1664): pack weights. Also resets the grid barrier.
// ---------------------------------------------------------------------------
__global__ void __launch_bounds__(256) setup_kernel(
    const float* __restrict__ X,  const float* __restrict__ Wa,
    const float* __restrict__ ba, const float* __restrict__ Wq,
    const float* __restrict__ Wk, const float* __restrict__ Wv,
    const float* __restrict__ Wg, const float* __restrict__ Wo)
{
    if (blockIdx.x == 0 && threadIdx.x == 0) g_bar = 0;

    if (blockIdx.x < 1024) {
        int row  = (blockIdx.x * 256 + threadIdx.x) >> 5;
        int lane = threadIdx.x & 31;
        const float* xr = X + (size_t)row * DD;
        int c0 = lane * 16;

        float xv[16];
        #pragma unroll
        for (int i = 0; i < 4; i++) {
            float4 v = *(const float4*)&xr[c0 + i * 4];
            xv[i*4+0] = v.x; xv[i*4+1] = v.y; xv[i*4+2] = v.z; xv[i*4+3] = v.w;
        }

        float4 acc = make_float4(0.f, 0.f, 0.f, 0.f);
        #pragma unroll
        for (int i = 0; i < 16; i++) {
            float4 w = *(const float4*)&Wa[(size_t)(c0 + i) * 4];
            acc.x += xv[i] * w.x; acc.y += xv[i] * w.y;
            acc.z += xv[i] * w.z; acc.w += xv[i] * w.w;
        }

        uint32_t hi[8], lo[8];
        #pragma unroll
        for (int i = 0; i < 8; i++) split2(xv[2*i], xv[2*i+1], hi[i], lo[i]);

        size_t base = (size_t)row * 64 + lane * 2;
        g_xhi[base + 0] = make_uint4(hi[0], hi[1], hi[2], hi[3]);
        g_xhi[base + 1] = make_uint4(hi[4], hi[5], hi[6], hi[7]);
        g_xlo[base + 0] = make_uint4(lo[0], lo[1], lo[2], lo[3]);
        g_xlo[base + 1] = make_uint4(lo[4], lo[5], lo[6], lo[7]);

        #pragma unroll
        for (int off = 16; off > 0; off >>= 1) {
            acc.x += __shfl_down_sync(0xffffffffu, acc.x, off);
            acc.y += __shfl_down_sync(0xffffffffu, acc.y, off);
            acc.z += __shfl_down_sync(0xffffffffu, acc.z, off);
            acc.w += __shfl_down_sync(0xffffffffu, acc.w, off);
        }
        if (lane == 0) {
            float zz[4] = {acc.x + ba[0], acc.y + ba[1], acc.z + ba[2], acc.w + ba[3]};
            #pragma unroll
            for (int h = 0; h < 4; h++) {
                float z = zz[h];
                float sp = fmaxf(z, 0.f) + log1pf(expf(-fabsf(z)));
                g_a[h * M_ROWS + row] = -sp;
            }
        }
    } else {
        int idx = (blockIdx.x - 1024) * 256 + threadIdx.x;
        if (idx < 131072) {
            int k = idx >> 8, n = idx & 255;
            float v;
            if      (n < 64)  v = Wq[k*64 + n];
            else if (n < 128) v = Wk[k*64 + (n-64)];
            else if (n < 192) v = Wv[k*64 + (n-128)];
            else              v = Wg[k*64 + (n-192)];
            __nv_bfloat16 h = __float2bfloat16(v);
            __nv_bfloat16 l = __float2bfloat16(v - __bfloat162float(h));
            __nv_bfloat16* W = (__nv_bfloat16*)g_wcatT;
            W[(size_t)n * KQ +        k] = h;
            W[(size_t)n * KQ +  512 + k] = l;
            W[(size_t)n * KQ + 1024 + k] = h;
        } else {
            int j = idx - 131072;
            int k = j >> 9, n = j & 511;
            float v = Wo[(size_t)k * 512 + n];
            __nv_bfloat16 h = __float2bfloat16(v);
            __nv_bfloat16 l = __float2bfloat16(v - __bfloat162float(h));
            __nv_bfloat16* W = (__nv_bfloat16*)g_woT;
            W[(size_t)n * KO +       k] = h;
            W[(size_t)n * KO +  64 + k] = l;
            W[(size_t)n * KO + 128 + k] = h;
        }
    }
}

// ---------------------------------------------------------------------------
// K2: qkvg GEMM, 512 threads. BM=64, BN=256, grid (128 mtiles) = one wave.
// A read ONCE. Warps 2m x 8n, warp tile 32x32. 3-stage pipeline,
// 40KB/stage: A 8KB | B 32KB. Epilogue: wn<128 -> bid (via smem), else v|g.
// ---------------------------------------------------------------------------
__global__ void __launch_bounds__(512) gemm_qkvg_mma() {
    extern __shared__ __align__(1024) char smem[];
    uint32_t sb = smem_u32(smem);
    int tid = threadIdx.x, wid = tid >> 5, lane = tid & 31;
    int mtile = blockIdx.x;

    const __nv_bfloat16* B = (const __nv_bfloat16*)g_wcatT;   // all 256 n-rows
    size_t aoff = (size_t)mtile * 64 * 512;
    auto getA = [&](int kc) -> const __nv_bfloat16* {
        const __nv_bfloat16* base = (kc < 16) ? (const __nv_bfloat16*)g_xhi
                                              : (const __nv_bfloat16*)g_xlo;
        int kk = (kc < 8) ? kc : ((kc < 16) ? kc - 8 : kc - 16);
        return base + aoff + kk * 64;
    };

    int wm = (wid & 1) * 32, wn = (wid >> 1) * 32;
    int lr = lane & 7, sel = lane >> 3;
    int arow = wm + lr + (sel & 1) * 8;
    int acol = (sel >> 1) * 16;
    int brow = wn + lr;
    int bcol = (sel & 1) * 16;

    float acc[2][4][4] = {};

    auto load = [&](int kc, int s) {
        uint32_t base = sb + (uint32_t)s * 40960;
        const __nv_bfloat16* Ak = getA(kc);
        const __nv_bfloat16* Bk = B + kc * 64;
        {   // A: 64 rows x 64 cols = 512 uint4, 1 per thread
            int r = tid >> 3, ch = tid & 7;
            cpa16(base + SWZ((uint32_t)(r * 128 + ch * 16)),
                  Ak + (size_t)r * 512 + ch * 8);
        }
        #pragma unroll
        for (int j = 0; j < 4; j++) {   // B: 256 rows x 64 cols = 2048 uint4
            int idx = j * 512 + tid;
            int r = idx >> 3, ch = idx & 7;
            cpa16(base + 8192 + SWZ((uint32_t)(r * 128 + ch * 16)),
                  Bk + (size_t)r * KQ + ch * 8);
        }
        CP_COMMIT();
    };

    load(0, 0);
    load(1, 1);

    for (int kc = 0; kc < 24; kc++) {
        asm volatile("cp.async.wait_group 1;" ::: "memory");
        __syncthreads();
        if (kc + 2 < 24) load(kc + 2, (kc + 2) % 3); else CP_COMMIT();

        uint32_t Ab = sb + (uint32_t)(kc % 3) * 40960;
        uint32_t Bb = Ab + 8192;
        #pragma unroll
        for (int ks = 0; ks < 4; ks++) {
            uint32_t a[2][4], b[4][2];
            #pragma unroll
            for (int mf = 0; mf < 2; mf++) {
                uint32_t addr = Ab + SWZ((uint32_t)((arow + mf * 16) * 128 + acol + ks * 32));
                asm volatile("ldmatrix.sync.aligned.m8n8.x4.shared.b16 {%0,%1,%2,%3}, [%4];"
                    : "=r"(a[mf][0]), "=r"(a[mf][1]), "=r"(a[mf][2]), "=r"(a[mf][3])
                    : "r"(addr));
            }
            #pragma unroll
            for (int nf = 0; nf < 4; nf++) {
                uint32_t addr = Bb + SWZ((uint32_t)((brow + nf * 8) * 128 + bcol + ks * 32));
                asm volatile("ldmatrix.sync.aligned.m8n8.x2.shared.b16 {%0,%1}, [%2];"
                    : "=r"(b[nf][0]), "=r"(b[nf][1])
                    : "r"(addr));
            }
            #pragma unroll
            for (int mf = 0; mf < 2; mf++)
                #pragma unroll
                for (int nf = 0; nf < 4; nf++)
                    mma_bf16(acc[mf][nf], a[mf], b[nf]);
        }
    }
    CP_WAIT0();

    int er = lane >> 2, ec = (lane & 3) * 2;
    int m0 = mtile * 64;

    __syncthreads();                       // mainloop smem free
    float* S = (float*)smem;               // 64x128 fp32 = 32KB, xor-swizzled

    if (wn < 128) {
        int xm = er << 4;
        #pragma unroll
        for (int mf = 0; mf < 2; mf++)
            #pragma unroll
            for (int nf = 0; nf < 4; nf++) {
                int r = wm + mf * 16 + er;
                int c = (wn + nf * 8 + ec) ^ xm;
                *(float2*)&S[r * 128 + c]       = make_float2(acc[mf][nf][0], acc[mf][nf][1]);
                *(float2*)&S[(r + 8) * 128 + c] = make_float2(acc[mf][nf][2], acc[mf][nf][3]);
            }
    } else {
        #pragma unroll
        for (int mf = 0; mf < 2; mf++)
            #pragma unroll
            for (int nf = 0; nf < 4; nf++) {
                int r = m0 + wm + mf * 16 + er;
                int c = (wn - 128) + nf * 8 + ec;
                *(float2*)&g_vg[(size_t)r * 128 + c]       = make_float2(acc[mf][nf][0], acc[mf][nf][1]);
                *(float2*)&g_vg[(size_t)(r + 8) * 128 + c] = make_float2(acc[mf][nf][2], acc[mf][nf][3]);
            }
    }
    __syncthreads();

    if (tid < 256) {
        int m = tid >> 2, h = tid & 3;     // 64 rows x 4 heads
        int x = (m & 7) << 4;
        const float* q = &S[m * 128 + ((h * 16) ^ x)];
        const float* k = &S[m * 128 + ((64 + h * 16) ^ x)];
        float s = 0.f;
        #pragma unroll
        for (int i = 0; i < 16; i++) s += q[i] * k[i];
        g_bid[(size_t)h * M_ROWS + m0 + m] = s * 0.25f;
    }
}

// ---------------------------------------------------------------------------
// K3: FUSED scan with grid barrier. 128 blocks x 128 threads (4 chunks/block,
// all same bh). Per-lane states, p, and v stay in REGISTERS across the barrier.
// ---------------------------------------------------------------------------
__global__ void __launch_bounds__(128) scan_fused(const float* __restrict__ bg) {
    __shared__ float sInc[32][20];   // inclusive global-frame chunk states + cumA

    int warp = threadIdx.x >> 5, lane = threadIdx.x & 31;
    int chunk = blockIdx.x * 4 + warp;
    int bh = chunk >> 5, c = chunk & 31;
    int b = bh >> 2, h = bh & 3;
    int row = b * TT + c * 64 + lane * 2;

    // ---- Phase 1: local logits + 2-step state + warp inclusive scan ----
    const float* A   = g_a   + (size_t)h * M_ROWS;
    const float* BID = g_bid + (size_t)h * M_ROWS;
    float a0 = A[row], a1 = A[row + 1];
    float la = a0 + a1;
    float incl = la;
    #pragma unroll
    for (int off = 1; off < 32; off <<= 1) {
        float o = __shfl_up_sync(0xffffffffu, incl, off);
        if (lane >= off) incl += o;
    }
    float exc = incl - la;
    float p0 = BID[row]     - (exc + a0);
    float p1 = BID[row + 1] - (exc + a0 + a1);

    float vvA[16], vvB[16];
    {
        const float* v0 = &g_vg[(size_t)row * 128 + h * 16];
        const float* v1 = &g_vg[(size_t)(row + 1) * 128 + h * 16];
        #pragma unroll
        for (int i = 0; i < 4; i++) {
            float4 t0 = *(const float4*)&v0[i * 4];
            float4 t1 = *(const float4*)&v1[i * 4];
            vvA[i*4+0]=t0.x; vvA[i*4+1]=t0.y; vvA[i*4+2]=t0.z; vvA[i*4+3]=t0.w;
            vvB[i*4+0]=t1.x; vvB[i*4+1]=t1.y; vvB[i*4+2]=t1.z; vvB[i*4+3]=t1.w;
        }
    }

    float m = MSENT, d = 0.f, n[16];
    #pragma unroll
    for (int i = 0; i < 16; i++) n[i] = 0.f;
    sm_step_r(m, d, n, p0, vvA);
    sm_step_r(m, d, n, p1, vvB);

    #pragma unroll
    for (int off = 1; off < 32; off <<= 1) {
        float om, od, on[16];
        WSHFL_STATE(om, od, on, off);
        if (lane >= off) sm_comb(m, d, n, om, od, on);
    }

    if (lane == 31) {
        g_aggA[chunk] = incl;
        g_topm[chunk] = m; g_topd[chunk] = d;
        #pragma unroll
        for (int i = 0; i < 16; i++) g_topn[i][chunk] = n[i];
        __threadfence();
    }
    __syncthreads();

    // ---- grid barrier (all 128 blocks co-resident: grid <= #SMs) ----
    if (threadIdx.x == 0) {
        atomicAdd(&g_bar, 1);
        while (*((volatile int*)&g_bar) < (int)gridDim.x) { }
        __threadfence();
    }
    __syncthreads();

    // ---- warp 0: bh-wide inclusive prefix over chunk tops (once/block) ----
    if (warp == 0) {
        int cch = bh * 32 + lane;
        float sA = g_aggA[cch];
        float m = g_topm[cch], d = g_topd[cch], n[16];   // shadows outer
        #pragma unroll
        for (int i = 0; i < 16; i++) n[i] = g_topn[i][cch];

        float cum = sA;
        #pragma unroll
        for (int off = 1; off < 32; off <<= 1) {
            float o = __shfl_up_sync(0xffffffffu, cum, off);
            if (lane >= off) cum += o;
        }
        m -= (cum - sA);                  // -> global frame
        #pragma unroll
        for (int off = 1; off < 32; off <<= 1) {
            float om, od, on[16];
            WSHFL_STATE(om, od, on, off);
            if (lane >= off) sm_comb(m, d, n, om, od, on);
        }
        sInc[lane][0] = m; sInc[lane][1] = d;
        #pragma unroll
        for (int i = 0; i < 16; i++) sInc[lane][2 + i] = n[i];
        sInc[lane][18] = cum;
    }

    // ---- per-lane exclusive from register state ----
    float em = __shfl_up_sync(0xffffffffu, m, 1);
    float ed = __shfl_up_sync(0xffffffffu, d, 1);
    float en[16];
    #pragma unroll
    for (int i = 0; i < 16; i++) en[i] = __shfl_up_sync(0xffffffffu, n[i], 1);
    if (lane == 0) {
        em = MSENT; ed = 0.f;
        #pragma unroll
        for (int i = 0; i < 16; i++) en[i] = 0.f;
    }

    __syncthreads();

    float Pm, Pd, Pn[16];
    if (c == 0) {
        Pm = MSENT; Pd = 0.f;
        #pragma unroll
        for (int i = 0; i < 16; i++) Pn[i] = 0.f;
    } else {
        Pm = sInc[c - 1][0] + sInc[c - 1][18];    // + prefA -> local frame
        Pd = sInc[c - 1][1];
        #pragma unroll
        for (int i = 0; i < 16; i++) Pn[i] = sInc[c - 1][2 + i];
    }
    sm_comb(em, ed, en, Pm, Pd, Pn);

    float bgv[16];
    #pragma unroll
    for (int i = 0; i < 16; i++) bgv[i] = bg[h * 16 + i];

    // ---- replay (v in registers) + gate + z split ----
    #pragma unroll
    for (int j = 0; j < 2; j++) {
        int r = row + j;
        sm_step_r(em, ed, en, (j == 0) ? p0 : p1, (j == 0) ? vvA : vvB);
        float inv = __fdividef(1.f, ed);

        const float* gp = &g_vg[(size_t)r * 128 + 64 + h * 16];
        float4 g0 = *(const float4*)&gp[0],  g1 = *(const float4*)&gp[4];
        float4 g2 = *(const float4*)&gp[8],  g3 = *(const float4*)&gp[12];
        float gl16[16] = {g0.x,g0.y,g0.z,g0.w, g1.x,g1.y,g1.z,g1.w,
                          g2.x,g2.y,g2.z,g2.w, g3.x,g3.y,g3.z,g3.w};
        float out[16];
        #pragma unroll
        for (int i = 0; i < 16; i++) {
            float gate = __fdividef(1.f, 1.f + __expf(-(gl16[i] + bgv[i])));
            out[i] = en[i] * inv * gate;
        }
        uint32_t hi[8], lo[8];
        #pragma unroll
        for (int i = 0; i < 8; i++) split2(out[2*i], out[2*i+1], hi[i], lo[i]);
        size_t zb = (size_t)r * 8 + h * 2;
        g_zhi[zb + 0] = make_uint4(hi[0], hi[1], hi[2], hi[3]);
        g_zhi[zb + 1] = make_uint4(hi[4], hi[5], hi[6], hi[7]);
        g_zlo[zb + 0] = make_uint4(lo[0], lo[1], lo[2], lo[3]);
        g_zlo[zb + 1] = make_uint4(lo[4], lo[5], lo[6], lo[7]);
    }
}

// ---------------------------------------------------------------------------
// K4: out = z @ Wo, 512 threads, BM=128, BN=256, grid (2,64) = one wave.
// FULL PREFETCH: all 3 K-chunks loaded up front into 3 stages (144KB smem),
// drained with wait_group 2/1/0. Warps 4m x 4n, warp tile 32x64.
// ---------------------------------------------------------------------------
__global__ void __launch_bounds__(512) gemm_out_mma(float* __restrict__ O) {
    extern __shared__ __align__(1024) char smem[];
    uint32_t sb = smem_u32(smem);
    int tid = threadIdx.x, wid = tid >> 5, lane = tid & 31;
    int ntile = blockIdx.x, mtile = blockIdx.y;

    const __nv_bfloat16* B = ((const __nv_bfloat16*)g_woT) + (size_t)ntile * 256 * KO;
    size_t aoff = (size_t)mtile * 128 * 64;   // bf16 elements

    int wm = (wid & 3) * 32, wn = (wid >> 2) * 64;
    int lr = lane & 7, sel = lane >> 3;
    int arow = wm + lr + (sel & 1) * 8;
    int acol = (sel >> 1) * 16;
    int brow = wn + lr;
    int bcol = (sel & 1) * 16;

    float acc[2][8][4] = {};

    auto getA = [&](int kc) -> const __nv_bfloat16* {
        return ((kc < 2) ? (const __nv_bfloat16*)g_zhi
                         : (const __nv_bfloat16*)g_zlo) + aoff;   // cast FIRST, then add
    };
    auto load = [&](int kc) {
        uint32_t base = sb + (uint32_t)kc * 49152;
        const __nv_bfloat16* Ak = getA(kc);
        const __nv_bfloat16* Bk = B + kc * 64;
        #pragma unroll
        for (int j = 0; j < 2; j++) {              // A: 1024 uint4 (16KB)
            int idx = tid * 2 + j;
            int r = idx >> 3, ch = idx & 7;
            cpa16(base + SWZ((uint32_t)(r * 128 + ch * 16)),
                  Ak + (size_t)r * 64 + ch * 8);
        }
        #pragma unroll
        for (int j = 0; j < 4; j++) {              // B: 2048 uint4 (32KB)
            int idx = j * 512 + tid;
            int r = idx >> 3, ch = idx & 7;
            cpa16(base + 16384 + SWZ((uint32_t)(r * 128 + ch * 16)),
                  Bk + (size_t)r * KO + ch * 8);
        }
        CP_COMMIT();
    };

    // issue ALL loads up front (max MLP)
    load(0); load(1); load(2);

    auto compute = [&](int kc) {
        uint32_t Ab = sb + (uint32_t)kc * 49152;
        uint32_t Bb = Ab + 16384;
        #pragma unroll
        for (int ks = 0; ks < 4; ks++) {
            uint32_t a[2][4], b[8][2];
            #pragma unroll
            for (int mf = 0; mf < 2; mf++) {
                uint32_t addr = Ab + SWZ((uint32_t)((arow + mf * 16) * 128 + acol + ks * 32));
                asm volatile("ldmatrix.sync.aligned.m8n8.x4.shared.b16 {%0,%1,%2,%3}, [%4];"
                    : "=r"(a[mf][0]), "=r"(a[mf][1]), "=r"(a[mf][2]), "=r"(a[mf][3])
                    : "r"(addr));
            }
            #pragma unroll
            for (int nf = 0; nf < 8; nf++) {
                uint32_t addr = Bb + SWZ((uint32_t)((brow + nf * 8) * 128 + bcol + ks * 32));
                asm volatile("ldmatrix.sync.aligned.m8n8.x2.shared.b16 {%0,%1}, [%2];"
                    : "=r"(b[nf][0]), "=r"(b[nf][1])
                    : "r"(addr));
            }
            #pragma unroll
            for (int mf = 0; mf < 2; mf++)
                #pragma unroll
                for (int nf = 0; nf < 8; nf++)
                    mma_bf16(acc[mf][nf], a[mf], b[nf]);
        }
    };

    asm volatile("cp.async.wait_group 2;" ::: "memory");
    __syncthreads();
    compute(0);
    asm volatile("cp.async.wait_group 1;" ::: "memory");
    __syncthreads();
    compute(1);
    asm volatile("cp.async.wait_group 0;" ::: "memory");
    __syncthreads();
    compute(2);

    int er = lane >> 2, ec = (lane & 3) * 2;
    int m0 = mtile * 128, n0 = ntile * 256;

    #pragma unroll
    for (int mf = 0; mf < 2; mf++)
        #pragma unroll
        for (int nf = 0; nf < 8; nf++) {
            int r = m0 + wm + mf * 16 + er;
            int c = n0 + wn + nf * 8 + ec;
            *(float2*)&O[(size_t)r * 512 + c]       = make_float2(acc[mf][nf][0], acc[mf][nf][1]);
            *(float2*)&O[(size_t)(r + 8) * 512 + c] = make_float2(acc[mf][nf][2], acc[mf][nf][3]);
        }
}

// ---------------------------------------------------------------------------
extern "C" void kernel_launch(void* const* d_in, const int* in_sizes, int n_in,
                              void* d_out, int out_size) {
    const float* x  = (const float*)d_in[0];
    const float* Wq = (const float*)d_in[1];
    const float* Wk = (const float*)d_in[2];
    const float* Wv = (const float*)d_in[3];
    const float* Wa = (const float*)d_in[4];
    const float* ba = (const float*)d_in[5];
    const float* Wg = (const float*)d_in[6];
    const float* bg = (const float*)d_in[7];
    const float* Wo = (const float*)d_in[8];
    float* out = (float*)d_out;

    cudaFuncSetAttribute(gemm_qkvg_mma, cudaFuncAttributeMaxDynamicSharedMemorySize, 122880);
    cudaFuncSetAttribute(gemm_out_mma,  cudaFuncAttributeMaxDynamicSharedMemorySize, 147456);

    setup_kernel<<<1664, 256>>>(x, Wa, ba, Wq, Wk, Wv, Wg, Wo);      // #1
    gemm_qkvg_mma<<<128, 512, 122880>>>();                            // #2
    scan_fused<<<128, 128>>>(bg);                                     // #3
    gemm_out_mma<<<dim3(2, 64), 512, 147456>>>(out);                  // #4
}